// round 8
// baseline (speedup 1.0000x reference)
#include <cuda_runtime.h>
#include <cstdint>
#include <math.h>

#define NUM_ROIS 333
#define BATCH    512
#define N_REG    300
#define N_CLS    180
#define EPSV     1e-5f
#define SLOPEV   0.3f
#define SPLITK   24

// -------- static device scratch (no allocations allowed) --------
__device__ int   g_base[NUM_ROIS];
__device__ int   g_size[NUM_ROIS];
__device__ int   g_red [NUM_ROIS];
__device__ int   g_off [NUM_ROIS];
__device__ int   g_order[NUM_ROIS];
__device__ __align__(16) float g_partial[SPLITK * BATCH * N_REG];

typedef unsigned long long u64;

__device__ __forceinline__ u64 fma2(u64 a, u64 b, u64 c) {
    u64 d;
    asm("fma.rn.f32x2 %0, %1, %2, %3;" : "=l"(d) : "l"(a), "l"(b), "l"(c));
    return d;
}
__device__ __forceinline__ float2 unpack2(u64 v) {
    float lo, hi;
    asm("mov.b64 {%0, %1}, %2;" : "=f"(lo), "=f"(hi) : "l"(v));
    return make_float2(lo, hi);
}
__device__ __forceinline__ unsigned sptr(const void* p) {
    return (unsigned)__cvta_generic_to_shared(p);
}
__device__ __forceinline__ void cpa4(unsigned dst, const void* src) {
    asm volatile("cp.async.ca.shared.global [%0], [%1], 4;" :: "r"(dst), "l"(src));
}
__device__ __forceinline__ void cp_commit() { asm volatile("cp.async.commit_group;"); }
__device__ __forceinline__ void cp_wait1()  { asm volatile("cp.async.wait_group 1;" ::: "memory"); }

// ============================================================
// Setup: per-ROI meta + size-descending schedule
// ============================================================
__global__ void setup_kernel(const int* __restrict__ idx,
                             const int* __restrict__ src_index,
                             int max_in, int max_out, int total, int C) {
    int t = threadIdx.x;
    __shared__ int s_size[NUM_ROIS];
    for (int r = t; r < NUM_ROIS; r += blockDim.x) {
        const int* row = idx + (size_t)r * max_in;
        int lo = 0, hi = max_in;
        while (lo < hi) {                    // first k with row[k] == total
            int mid = (lo + hi) >> 1;
            if (row[mid] == total) hi = mid; else lo = mid + 1;
        }
        g_size[r] = lo;
        s_size[r] = lo;
        g_base[r] = row[0];
    }
    __shared__ int cnt[NUM_ROIS];
    for (int r = t; r < NUM_ROIS; r += blockDim.x) cnt[r] = 0;
    __syncthreads();
    for (int p = t; p < C; p += blockDim.x)
        atomicAdd(&cnt[src_index[p] / max_out], 1);
    __syncthreads();
    if (t == 0) {
        int off = 0;
        for (int r = 0; r < NUM_ROIS; r++) {
            g_red[r] = cnt[r];
            g_off[r] = off;
            off += cnt[r];
        }
    }
    // size-descending rank (deterministic tie-break by index)
    for (int r = t; r < NUM_ROIS; r += blockDim.x) {
        int sz = s_size[r];
        int rank = 0;
        for (int j = 0; j < NUM_ROIS; j++) {
            int sj = s_size[j];
            if (sj > sz || (sj == sz && j < r)) rank++;
        }
        g_order[rank] = r;
    }
}

// ============================================================
// Stage A: per-ROI GEMM, tile 512 batch x 32 out, per-thread 16b x 4o
// grid: (NUM_ROIS sorted, 2 o-tiles)
// ============================================================
#define A_XSTR 516                       // 512 data + 4 pad
#define A_WSTR 68                        // 64 dup floats + 4 pad
#define A_XSZ  (16 * A_XSTR)             // 8256
#define A_WSZ  (16 * A_WSTR)             // 1088
#define A_SMEM ((2 * A_XSZ + 2 * A_WSZ) * 4)   // 74752 bytes

__global__ __launch_bounds__(256, 2)
void roi_enc_kernel(const float* __restrict__ x, const float* __restrict__ W_enc,
                    const float* __restrict__ b_enc, const float* __restrict__ gamma,
                    const float* __restrict__ beta, const float* __restrict__ rmean,
                    const float* __restrict__ rvar, float* __restrict__ concat_out,
                    int total, int max_in, int max_out, int C)
{
    extern __shared__ float sm[];
    float* Xs = sm;                       // [2][16][A_XSTR]
    float* Ws = sm + 2 * A_XSZ;           // [2][16][A_WSTR]

    const int r    = g_order[blockIdx.x];
    const int ot   = blockIdx.y * 32;
    const int size = g_size[r];
    const int red  = g_red[r];
    const int base = g_base[r];
    const int ooff = g_off[r];
    if (ot >= red) return;                // uniform per block

    const int tid   = threadIdx.x;
    const int blane = tid >> 3;           // 0..31 : 16 batches each
    const int olane = tid & 7;            // 0..7  : 4 outputs each
    const int fk    = tid & 15;           // fill: k within tile
    const int fr0   = tid >> 4;           // fill: base row (0..15)

    const float* xg = x + base;
    const float* wg = W_enc + (size_t)r * max_out * max_in;
    const unsigned xs_u = sptr(Xs);

    const int nt = (size + 15) >> 4;

    u64 acc[8][4];
    #pragma unroll
    for (int i = 0; i < 8; i++)
        #pragma unroll
        for (int j = 0; j < 4; j++) acc[i][j] = 0ull;

    float wr[2];

    auto fillX = [&](int t, int st) {
        int kg = t * 16 + fk;
        if (kg < size) {
            const float* src = xg + kg;
            unsigned dst = xs_u + (unsigned)(st * A_XSZ + fk * A_XSTR) * 4u;
            #pragma unroll
            for (int it = 0; it < 32; it++) {
                int b = fr0 + it * 16;
                cpa4(dst + (unsigned)b * 4u, src + (size_t)b * total);
            }
        } else {
            float* d = Xs + st * A_XSZ + fk * A_XSTR;
            #pragma unroll
            for (int it = 0; it < 32; it++) d[fr0 + it * 16] = 0.f;
        }
    };
    auto ldgW = [&](int t) {
        int kg = t * 16 + fk;
        #pragma unroll
        for (int it = 0; it < 2; it++) {
            int o = ot + fr0 + it * 16;
            wr[it] = (o < max_out && kg < size) ? wg[(size_t)o * max_in + kg] : 0.f;
        }
    };
    auto stsW = [&](int st) {
        float* d = Ws + st * A_WSZ + fk * A_WSTR;
        #pragma unroll
        for (int it = 0; it < 2; it++) {
            int ol = fr0 + it * 16;       // local o in [0,32)
            *(float2*)(d + ol * 2) = make_float2(wr[it], wr[it]);
        }
    };
    auto compute = [&](int st) {
        const float* xb = Xs + st * A_XSZ + blane * 16;
        const float* wb = Ws + st * A_WSZ + olane * 8;
        #pragma unroll
        for (int kk = 0; kk < 16; kk++) {
            const ulonglong2* xp = (const ulonglong2*)(xb + kk * A_XSTR);
            const ulonglong2* wp = (const ulonglong2*)(wb + kk * A_WSTR);
            ulonglong2 x01 = xp[0], x23 = xp[1], x45 = xp[2], x67 = xp[3];
            ulonglong2 w01 = wp[0], w23 = wp[1];
            u64 xv[8] = {x01.x, x01.y, x23.x, x23.y, x45.x, x45.y, x67.x, x67.y};
            u64 wv[4] = {w01.x, w01.y, w23.x, w23.y};
            #pragma unroll
            for (int i = 0; i < 8; i++)
                #pragma unroll
                for (int j = 0; j < 4; j++)
                    acc[i][j] = fma2(xv[i], wv[j], acc[i][j]);
        }
    };

    // ---- pipelined mainloop (2-stage) ----
    fillX(0, 0); cp_commit();
    ldgW(0);
    if (nt > 1) fillX(1, 1);
    cp_commit();
    stsW(0);
    if (nt > 1) ldgW(1);
    cp_wait1();
    __syncthreads();

    for (int t = 0; t < nt; t++) {
        int st = t & 1;
        compute(st);
        __syncthreads();
        if (t + 2 < nt) fillX(t + 2, st);
        cp_commit();
        if (t + 1 < nt) stsW(st ^ 1);
        if (t + 2 < nt) ldgW(t + 2);
        cp_wait1();
        __syncthreads();
    }

    // ---- epilogue: BN + leaky, smem transpose, coalesced store ----
    // per-thread BN coefficients for its 4 o's: y = z*a + c, then leaky
    float ca[4], cc[4];
    const int ol0 = olane * 4;
    #pragma unroll
    for (int j = 0; j < 4; j++) {
        int o = ot + ol0 + j;
        if (o < red) {
            size_t po = (size_t)r * max_out + o;
            float inv = rsqrtf(rvar[po] + EPSV);
            float a   = gamma[po] * inv;
            ca[j] = a;
            cc[j] = (b_enc[po] - rmean[po]) * a + beta[po];
        } else { ca[j] = 0.f; cc[j] = 0.f; }
    }

    float* Ysm = sm;   // reuse: 128*33 = 4224 floats
    for (int q = 0; q < 4; q++) {         // batch quarters of 128
        __syncthreads();
        if ((blane >> 3) == q) {
            int bl0 = (blane & 7) * 16;
            #pragma unroll
            for (int i = 0; i < 8; i++) {
                float2 p[4];
                #pragma unroll
                for (int j = 0; j < 4; j++) p[j] = unpack2(acc[i][j]);
                #pragma unroll
                for (int j = 0; j < 4; j++) {
                    float y0 = fmaf(p[j].x, ca[j], cc[j]);
                    float y1 = fmaf(p[j].y, ca[j], cc[j]);
                    y0 = (y0 > 0.f) ? y0 : SLOPEV * y0;
                    y1 = (y1 > 0.f) ? y1 : SLOPEV * y1;
                    Ysm[(bl0 + 2 * i)     * 33 + ol0 + j] = y0;
                    Ysm[(bl0 + 2 * i + 1) * 33 + ol0 + j] = y1;
                }
            }
        }
        __syncthreads();
        for (int p = tid; p < 128 * 32; p += 256) {
            int bl = p >> 5, o = p & 31;
            if (ot + o < red)
                concat_out[(size_t)(q * 128 + bl) * C + ooff + ot + o] =
                    Ysm[bl * 33 + o];
        }
    }
}

// ============================================================
// Stage B: partials = concat_out @ W_reg^T (split-K)
// 128 threads, tile 256m x 64n, per-thread 16m x 8n
// ============================================================
#define B_ASTR 260                       // 256 + 4 pad
#define B_WSTR 132                       // 128 dup floats + 4 pad
#define B_ASZ  (16 * B_ASTR)             // 4160
#define B_WSZ  (16 * B_WSTR)             // 2112
#define B_SMEM ((2 * B_ASZ + 2 * B_WSZ) * 4)   // 50176 bytes

__global__ __launch_bounds__(128, 2)
void reg_gemm_kernel(const float* __restrict__ A, const float* __restrict__ Wr, int C)
{
    extern __shared__ float sm[];
    float* As = sm;
    float* Bs = sm + 2 * B_ASZ;

    const int m0 = blockIdx.x * 256;
    const int n0 = blockIdx.y * 64;
    const int s  = blockIdx.z;
    const int chunk = (C + SPLITK - 1) / SPLITK;
    const int kbeg  = s * chunk;
    const int kend  = min(C, kbeg + chunk);

    const int tid   = threadIdx.x;
    const int mlane = tid >> 3;           // 0..15 : 16 m each
    const int nlane = tid & 7;            // 0..7  : 8 n each
    const int fk    = tid & 15;
    const int fr0   = tid >> 4;           // 0..7

    const unsigned as_u = sptr(As);

    u64 acc[8][8];
    #pragma unroll
    for (int i = 0; i < 8; i++)
        #pragma unroll
        for (int j = 0; j < 8; j++) acc[i][j] = 0ull;

    const int nt = (kend - kbeg + 15) >> 4;
    float wr[8];

    auto fillA = [&](int t, int st) {
        int kg = kbeg + t * 16 + fk;
        if (kg < kend) {
            unsigned dst = as_u + (unsigned)(st * B_ASZ + fk * B_ASTR) * 4u;
            const float* src = A + kg;
            #pragma unroll
            for (int it = 0; it < 32; it++) {
                int m = fr0 + it * 8;
                cpa4(dst + (unsigned)m * 4u, src + (size_t)(m0 + m) * C);
            }
        } else {
            float* d = As + st * B_ASZ + fk * B_ASTR;
            #pragma unroll
            for (int it = 0; it < 32; it++) d[fr0 + it * 8] = 0.f;
        }
    };
    auto ldgW = [&](int t) {
        int kg = kbeg + t * 16 + fk;
        #pragma unroll
        for (int it = 0; it < 8; it++) {
            int n = n0 + fr0 + it * 8;
            wr[it] = (n < N_REG && kg < kend) ? Wr[(size_t)n * C + kg] : 0.f;
        }
    };
    auto stsW = [&](int st) {
        float* d = Bs + st * B_WSZ + fk * B_WSTR;
        #pragma unroll
        for (int it = 0; it < 8; it++) {
            int nl = fr0 + it * 8;        // local n in [0,64)
            *(float2*)(d + nl * 2) = make_float2(wr[it], wr[it]);
        }
    };
    auto compute = [&](int st) {
        const float* xb = As + st * B_ASZ + mlane * 16;
        const float* wb = Bs + st * B_WSZ + nlane * 16;
        #pragma unroll
        for (int kk = 0; kk < 16; kk++) {
            const ulonglong2* xp = (const ulonglong2*)(xb + kk * B_ASTR);
            const ulonglong2* wp = (const ulonglong2*)(wb + kk * B_WSTR);
            ulonglong2 x01 = xp[0], x23 = xp[1], x45 = xp[2], x67 = xp[3];
            ulonglong2 w01 = wp[0], w23 = wp[1], w45 = wp[2], w67 = wp[3];
            u64 xv[8] = {x01.x, x01.y, x23.x, x23.y, x45.x, x45.y, x67.x, x67.y};
            u64 wv[8] = {w01.x, w01.y, w23.x, w23.y, w45.x, w45.y, w67.x, w67.y};
            #pragma unroll
            for (int i = 0; i < 8; i++)
                #pragma unroll
                for (int j = 0; j < 8; j++)
                    acc[i][j] = fma2(xv[i], wv[j], acc[i][j]);
        }
    };

    fillA(0, 0); cp_commit();
    ldgW(0);
    if (nt > 1) fillA(1, 1);
    cp_commit();
    stsW(0);
    if (nt > 1) ldgW(1);
    cp_wait1();
    __syncthreads();

    for (int t = 0; t < nt; t++) {
        int st = t & 1;
        compute(st);
        __syncthreads();
        if (t + 2 < nt) fillA(t + 2, st);
        cp_commit();
        if (t + 1 < nt) stsW(st ^ 1);
        if (t + 2 < nt) ldgW(t + 2);
        cp_wait1();
        __syncthreads();
    }

    // ---- write partials, vectorized along n ----
    const int nb = n0 + nlane * 8;
    #pragma unroll
    for (int i = 0; i < 8; i++) {
        float2 p[8];
        #pragma unroll
        for (int j = 0; j < 8; j++) p[j] = unpack2(acc[i][j]);
        #pragma unroll
        for (int h = 0; h < 2; h++) {
            int m = m0 + mlane * 16 + 2 * i + h;
            float* dst = g_partial + ((size_t)s * BATCH + m) * N_REG + nb;
            float v[8];
            #pragma unroll
            for (int j = 0; j < 8; j++) v[j] = h ? p[j].y : p[j].x;
            if (nb + 8 <= N_REG) {
                *(float4*)(dst)     = make_float4(v[0], v[1], v[2], v[3]);
                *(float4*)(dst + 4) = make_float4(v[4], v[5], v[6], v[7]);
            } else {
                #pragma unroll
                for (int j = 0; j < 8; j++)
                    if (nb + j < N_REG) dst[j] = v[j];
            }
        }
    }
}

// ============================================================
// Split-K reduce + bias -> reg_out  (600 CTAs, high MLP)
// ============================================================
__global__ void reg_reduce_kernel(const float* __restrict__ b_reg,
                                  float* __restrict__ reg_out) {
    int i = blockIdx.x * blockDim.x + threadIdx.x;
    if (i >= BATCH * N_REG) return;
    int n = i % N_REG;
    float sum = b_reg[n];
    #pragma unroll
    for (int k = 0; k < SPLITK; k++)
        sum += g_partial[(size_t)k * BATCH * N_REG + i];
    reg_out[i] = sum;
}

// ============================================================
// Stage C: cls GEMV + softmax.  128 CTAs x 4 rows.
// ============================================================
#define C_ROWS 4

__global__ __launch_bounds__(256)
void cls_softmax_kernel(const float* __restrict__ reg_out,
                        const float* __restrict__ W_cls,
                        const float* __restrict__ b_cls,
                        float* __restrict__ y_pred) {
    __shared__ float rows[C_ROWS][304];
    __shared__ float lg[C_ROWS][192];

    const int m0  = blockIdx.x * C_ROWS;
    const int tid = threadIdx.x;

    for (int p = tid; p < C_ROWS * N_REG; p += 256) {
        int mi = p / N_REG, n = p % N_REG;
        rows[mi][n] = reg_out[(size_t)(m0 + mi) * N_REG + n];
    }
    __syncthreads();

    for (int q = tid; q < C_ROWS * N_CLS; q += 256) {
        int mi = q / N_CLS, n = q % N_CLS;
        const float4* w  = (const float4*)(W_cls + (size_t)n * N_REG);
        const float4* rr = (const float4*)rows[mi];
        float s0 = b_cls[n], s1 = 0.f;
        #pragma unroll 5
        for (int k4 = 0; k4 < N_REG / 4; k4++) {
            float4 a = rr[k4];
            float4 b = __ldg(&w[k4]);
            s0 = fmaf(a.x, b.x, s0);
            s1 = fmaf(a.y, b.y, s1);
            s0 = fmaf(a.z, b.z, s0);
            s1 = fmaf(a.w, b.w, s1);
        }
        lg[mi][n] = s0 + s1;
    }
    __syncthreads();

    int w = tid >> 5, lane = tid & 31;
    if (w < C_ROWS) {
        int mi = w;
        float mx = -1e30f;
        for (int n = lane; n < N_CLS; n += 32) mx = fmaxf(mx, lg[mi][n]);
        #pragma unroll
        for (int off = 16; off > 0; off >>= 1)
            mx = fmaxf(mx, __shfl_xor_sync(0xffffffff, mx, off));
        float sum = 0.f;
        for (int n = lane; n < N_CLS; n += 32) {
            float e = expf(lg[mi][n] - mx);
            lg[mi][n] = e;
            sum += e;
        }
        #pragma unroll
        for (int off = 16; off > 0; off >>= 1)
            sum += __shfl_xor_sync(0xffffffff, sum, off);
        float inv = 1.f / sum;
        for (int n = lane; n < N_CLS; n += 32)
            y_pred[(size_t)(m0 + mi) * N_CLS + n] = lg[mi][n] * inv;
    }
}

// ============================================================
// Launch
// ============================================================
extern "C" void kernel_launch(void* const* d_in, const int* in_sizes, int n_in,
                              void* d_out, int out_size) {
    const float* x     = (const float*)d_in[0];
    const float* W_enc = (const float*)d_in[1];
    const float* b_enc = (const float*)d_in[2];
    const float* gamma = (const float*)d_in[3];
    const float* beta  = (const float*)d_in[4];
    const float* rmean = (const float*)d_in[5];
    const float* rvar  = (const float*)d_in[6];
    const float* W_reg = (const float*)d_in[7];
    const float* b_reg = (const float*)d_in[8];
    const float* W_cls = (const float*)d_in[9];
    const float* b_cls = (const float*)d_in[10];
    const int*   idx   = (const int*)d_in[11];
    const int*   srci  = (const int*)d_in[12];

    const int total   = in_sizes[0] / BATCH;
    const int max_out = in_sizes[2] / NUM_ROIS;
    const int max_in  = in_sizes[11] / NUM_ROIS;
    const int C       = in_sizes[12];

    float* out        = (float*)d_out;
    float* concat_out = out;
    float* reg_out    = out + (size_t)BATCH * C;
    float* y_pred     = reg_out + (size_t)BATCH * N_REG;

    cudaFuncSetAttribute(roi_enc_kernel,
                         cudaFuncAttributeMaxDynamicSharedMemorySize, A_SMEM);
    cudaFuncSetAttribute(reg_gemm_kernel,
                         cudaFuncAttributeMaxDynamicSharedMemorySize, B_SMEM);

    setup_kernel<<<1, 512>>>(idx, srci, max_in, max_out, total, C);

    dim3 gA(NUM_ROIS, 2);
    roi_enc_kernel<<<gA, 256, A_SMEM>>>(x, W_enc, b_enc, gamma, beta, rmean, rvar,
                                        concat_out, total, max_in, max_out, C);

    dim3 gB(BATCH / 256, (N_REG + 63) / 64, SPLITK);
    reg_gemm_kernel<<<gB, 128, B_SMEM>>>(concat_out, W_reg, C);

    reg_reduce_kernel<<<(BATCH * N_REG + 255) / 256, 256>>>(b_reg, reg_out);

    cls_softmax_kernel<<<BATCH / C_ROWS, 256>>>(reg_out, W_cls, b_cls, y_pred);
}

// round 9
// speedup vs baseline: 1.2322x; 1.2322x over previous
#include <cuda_runtime.h>
#include <cstdint>
#include <math.h>

#define NUM_ROIS 333
#define BATCH    512
#define N_REG    300
#define N_CLS    180
#define EPSV     1e-5f
#define SLOPEV   0.3f
#define SPLITK   24

// -------- static device scratch (no allocations allowed) --------
__device__ int   g_base[NUM_ROIS];
__device__ int   g_size[NUM_ROIS];
__device__ int   g_red [NUM_ROIS];
__device__ int   g_off [NUM_ROIS];
__device__ int   g_order[NUM_ROIS];
__device__ int   g_jobs[NUM_ROIS * 4];
__device__ int   g_njobs;
__device__ int   g_jobctr;
__device__ __align__(16) float g_partial[SPLITK * BATCH * N_REG];

typedef unsigned long long u64;

__device__ __forceinline__ u64 fma2(u64 a, u64 b, u64 c) {
    u64 d;
    asm("fma.rn.f32x2 %0, %1, %2, %3;" : "=l"(d) : "l"(a), "l"(b), "l"(c));
    return d;
}
__device__ __forceinline__ float2 unpack2(u64 v) {
    float lo, hi;
    asm("mov.b64 {%0, %1}, %2;" : "=f"(lo), "=f"(hi) : "l"(v));
    return make_float2(lo, hi);
}
__device__ __forceinline__ unsigned sptr(const void* p) {
    return (unsigned)__cvta_generic_to_shared(p);
}
__device__ __forceinline__ void cpa4(unsigned dst, const void* src) {
    asm volatile("cp.async.ca.shared.global [%0], [%1], 4;" :: "r"(dst), "l"(src));
}
__device__ __forceinline__ void cp_commit() { asm volatile("cp.async.commit_group;"); }
__device__ __forceinline__ void cp_wait1()  { asm volatile("cp.async.wait_group 1;" ::: "memory"); }

// ============================================================
// Setup: per-ROI meta, size-descending schedule, job queue
// ============================================================
__global__ void setup_kernel(const int* __restrict__ idx,
                             const int* __restrict__ src_index,
                             int max_in, int max_out, int total, int C) {
    int t = threadIdx.x;
    __shared__ int s_size[NUM_ROIS];
    for (int r = t; r < NUM_ROIS; r += blockDim.x) {
        const int* row = idx + (size_t)r * max_in;
        int lo = 0, hi = max_in;
        while (lo < hi) {                    // first k with row[k] == total
            int mid = (lo + hi) >> 1;
            if (row[mid] == total) hi = mid; else lo = mid + 1;
        }
        g_size[r] = lo;
        s_size[r] = lo;
        g_base[r] = row[0];
    }
    __shared__ int cnt[NUM_ROIS];
    for (int r = t; r < NUM_ROIS; r += blockDim.x) cnt[r] = 0;
    __syncthreads();
    for (int p = t; p < C; p += blockDim.x)
        atomicAdd(&cnt[src_index[p] / max_out], 1);
    __syncthreads();
    if (t == 0) {
        int off = 0;
        for (int r = 0; r < NUM_ROIS; r++) {
            g_red[r] = cnt[r];
            g_off[r] = off;
            off += cnt[r];
        }
    }
    __syncthreads();
    // size-descending rank (deterministic tie-break by index)
    for (int r = t; r < NUM_ROIS; r += blockDim.x) {
        int sz = s_size[r];
        int rank = 0;
        for (int j = 0; j < NUM_ROIS; j++) {
            int sj = s_size[j];
            if (sj > sz || (sj == sz && j < r)) rank++;
        }
        g_order[rank] = r;
    }
    __syncthreads();
    // job queue: valid (roi, batch-half, o-tile) in size-descending order
    if (t == 0) {
        int nj = 0;
        for (int p = 0; p < NUM_ROIS; p++) {
            int r   = g_order[p];
            int red = g_red[r];
            int not_ = (red > 32) ? 2 : 1;
            for (int ot = 0; ot < not_; ot++)
                for (int bh = 0; bh < 2; bh++)
                    g_jobs[nj++] = r | (bh << 9) | (ot << 10);
        }
        g_njobs  = nj;
        g_jobctr = 0;
    }
}

// ============================================================
// Stage A: persistent per-ROI GEMM (256 batch x 32 out per job)
// batch-packed f32x2, W duplicated in smem, cp.async double-buffered
// ============================================================
#define A_XSTR 260                       // 256 data + 4 pad
#define A_WSTR 100                       // 8 grp * 12 + 4 pad
#define A_XSZ  (16 * A_XSTR)             // 4160
#define A_WSZ  (16 * A_WSTR)             // 1600
#define A_SMEM ((2 * A_XSZ + 2 * A_WSZ) * 4 + 16)   // + job slot

__global__ __launch_bounds__(256, 2)
void roi_enc_kernel(const float* __restrict__ x, const float* __restrict__ W_enc,
                    const float* __restrict__ b_enc, const float* __restrict__ gamma,
                    const float* __restrict__ beta, const float* __restrict__ rmean,
                    const float* __restrict__ rvar, float* __restrict__ concat_out,
                    int total, int max_in, int max_out, int C)
{
    extern __shared__ float sm[];
    float* Xs = sm;                       // [2][A_XSZ]
    float* Ws = sm + 2 * A_XSZ;           // [2][A_WSZ]
    int*  jsm = (int*)(sm + 2 * A_XSZ + 2 * A_WSZ);

    const int tid = threadIdx.x;
    const int tb  = tid >> 3;             // 0..31 batch group (8 b each)
    const int to  = tid & 7;              // 0..7  out group   (4 o each)
    const int fk  = tid & 15;             // fill: fixed k within tile
    const int fr0 = tid >> 4;             // fill: base row

    const unsigned xs_u = sptr(Xs);
    const int njobs = g_njobs;

    while (true) {
        if (tid == 0) jsm[0] = atomicAdd(&g_jobctr, 1);
        __syncthreads();
        const int j = jsm[0];
        if (j >= njobs) break;
        const int job = g_jobs[j];
        const int r    = job & 511;
        const int b0   = ((job >> 9) & 1) * 256;
        const int ot   = ((job >> 10) & 1) * 32;
        const int size = g_size[r];
        const int red  = g_red[r];
        const int base = g_base[r];
        const int ooff = g_off[r];

        const float* xg = x + (size_t)b0 * total + base;
        const float* wg = W_enc + (size_t)r * max_out * max_in;
        const int nt = (size + 15) >> 4;

        u64 acc[4][4];
        #pragma unroll
        for (int i = 0; i < 4; i++)
            #pragma unroll
            for (int jj = 0; jj < 4; jj++) acc[i][jj] = 0ull;

        float wr[2];

        auto fillX = [&](int t, int st) {
            int kg = t * 16 + fk;
            if (kg < size) {
                const float* src = xg + kg;
                unsigned dst = xs_u + (unsigned)(st * A_XSZ + fk * A_XSTR) * 4u;
                #pragma unroll
                for (int it = 0; it < 16; it++) {
                    int b = fr0 + it * 16;
                    cpa4(dst + (unsigned)b * 4u, src + (size_t)b * total);
                }
            } else {
                float* d = Xs + st * A_XSZ + fk * A_XSTR;
                #pragma unroll
                for (int it = 0; it < 16; it++) d[fr0 + it * 16] = 0.f;
            }
        };
        auto ldgW = [&](int t) {
            int kg = t * 16 + fk;
            #pragma unroll
            for (int it = 0; it < 2; it++) {
                int o = ot + fr0 + it * 16;
                wr[it] = (o < max_out && kg < size) ? wg[(size_t)o * max_in + kg] : 0.f;
            }
        };
        auto stsW = [&](int st) {
            float* d = Ws + st * A_WSZ + fk * A_WSTR;
            #pragma unroll
            for (int it = 0; it < 2; it++) {
                int o = fr0 + it * 16;     // local o in [0,32)
                *(float2*)(d + (o >> 2) * 12 + (o & 3) * 2) = make_float2(wr[it], wr[it]);
            }
        };
        auto compute = [&](int st) {
            const float* xb = Xs + st * A_XSZ + tb * 8;
            const float* wb = Ws + st * A_WSZ + to * 12;
            #pragma unroll
            for (int kk = 0; kk < 16; kk++) {
                const ulonglong2* xp = (const ulonglong2*)(xb + kk * A_XSTR);
                const ulonglong2* wp = (const ulonglong2*)(wb + kk * A_WSTR);
                ulonglong2 x01 = xp[0], x23 = xp[1];
                ulonglong2 w01 = wp[0], w23 = wp[1];
                u64 xv[4] = {x01.x, x01.y, x23.x, x23.y};
                u64 wv[4] = {w01.x, w01.y, w23.x, w23.y};
                #pragma unroll
                for (int i = 0; i < 4; i++)
                    #pragma unroll
                    for (int jj = 0; jj < 4; jj++)
                        acc[i][jj] = fma2(xv[i], wv[jj], acc[i][jj]);
            }
        };

        // ---- pipelined mainloop (2-stage) ----
        fillX(0, 0); cp_commit();
        ldgW(0);
        if (nt > 1) fillX(1, 1);
        cp_commit();
        stsW(0);
        if (nt > 1) ldgW(1);
        cp_wait1();
        __syncthreads();

        for (int t = 0; t < nt; t++) {
            int st = t & 1;
            compute(st);
            __syncthreads();
            if (t + 2 < nt) fillX(t + 2, st);
            cp_commit();
            if (t + 1 < nt) stsW(st ^ 1);
            if (t + 2 < nt) ldgW(t + 2);
            cp_wait1();
            __syncthreads();
        }

        // ---- epilogue: BN + leaky, smem transpose, coalesced store ----
        float* Ysm = sm;   // reuse: 128*33 floats
        for (int half = 0; half < 2; half++) {
            __syncthreads();
            if ((tb >> 4) == half) {
                int bl = (tb & 15) * 8;
                #pragma unroll
                for (int jj = 0; jj < 4; jj++) {
                    int og = ot + to * 4 + jj;
                    if (og < red) {
                        size_t po = (size_t)r * max_out + og;
                        float be  = b_enc[po];
                        float ga  = gamma[po];
                        float bt  = beta[po];
                        float mn  = rmean[po];
                        float inv = rsqrtf(rvar[po] + EPSV);
                        int ol = to * 4 + jj;
                        #pragma unroll
                        for (int i = 0; i < 4; i++) {
                            float2 v = unpack2(acc[i][jj]);
                            float y0 = ga * (v.x + be - mn) * inv + bt;
                            float y1 = ga * (v.y + be - mn) * inv + bt;
                            y0 = (y0 > 0.f) ? y0 : SLOPEV * y0;
                            y1 = (y1 > 0.f) ? y1 : SLOPEV * y1;
                            Ysm[(bl + 2 * i)     * 33 + ol] = y0;
                            Ysm[(bl + 2 * i + 1) * 33 + ol] = y1;
                        }
                    }
                }
            }
            __syncthreads();
            for (int p = tid; p < 128 * 32; p += 256) {
                int bl = p >> 5, o = p & 31;
                int og = ot + o;
                if (og < red)
                    concat_out[(size_t)(b0 + half * 128 + bl) * C + ooff + og] =
                        Ysm[bl * 33 + o];
            }
        }
        __syncthreads();   // protect jsm + smem reuse before next job
    }
}

// ============================================================
// Stage B: reg_out partials = concat_out @ W_reg^T  (split-K)
// 128x128 tile, FFMA2 structure  (identical to R7 / 445us)
// ============================================================
#define B_ASTR 132                       // 128 + 4 pad
#define B_WSTR 324                       // 16 grp * 20 + 4 pad
#define B_ASZ  (16 * B_ASTR)             // 2112
#define B_WSZ  (16 * B_WSTR)             // 5184
#define B_SMEM ((2 * B_ASZ + 2 * B_WSZ) * 4)   // 58368 bytes

__global__ __launch_bounds__(256, 2)
void reg_gemm_kernel(const float* __restrict__ A, const float* __restrict__ Wr, int C)
{
    extern __shared__ float sm[];
    float* As = sm;
    float* Bs = sm + 2 * B_ASZ;

    const int m0 = blockIdx.x * 128;
    const int n0 = blockIdx.y * 128;
    const int s  = blockIdx.z;
    const int chunk = (C + SPLITK - 1) / SPLITK;
    const int kbeg  = s * chunk;
    const int kend  = min(C, kbeg + chunk);
    const int klen  = kend - kbeg;

    const int tid = threadIdx.x;
    const int tb  = tid >> 4;             // 0..15 m group
    const int to  = tid & 15;             // 0..15 n group
    const int fk  = tid & 15;
    const int fr0 = tid >> 4;

    const unsigned as_u = sptr(As);

    u64 acc[4][8];
    #pragma unroll
    for (int i = 0; i < 4; i++)
        #pragma unroll
        for (int j = 0; j < 8; j++) acc[i][j] = 0ull;

    if (klen > 0) {
        const int nt = (klen + 15) >> 4;
        float wr[8];

        auto fillA = [&](int t, int st) {
            int kg = kbeg + t * 16 + fk;
            if (kg < kend) {
                unsigned dst = as_u + (unsigned)(st * B_ASZ + fk * B_ASTR) * 4u;
                const float* src = A + kg;
                #pragma unroll
                for (int it = 0; it < 8; it++) {
                    int m = fr0 + it * 16;
                    cpa4(dst + (unsigned)m * 4u, src + (size_t)(m0 + m) * C);
                }
            } else {
                float* d = As + st * B_ASZ + fk * B_ASTR;
                #pragma unroll
                for (int it = 0; it < 8; it++) d[fr0 + it * 16] = 0.f;
            }
        };
        auto ldgW = [&](int t) {
            int kg = kbeg + t * 16 + fk;
            #pragma unroll
            for (int it = 0; it < 8; it++) {
                int n = n0 + fr0 + it * 16;
                wr[it] = (n < N_REG && kg < kend) ? Wr[(size_t)n * C + kg] : 0.f;
            }
        };
        auto stsW = [&](int st) {
            float* d = Bs + st * B_WSZ + fk * B_WSTR;
            #pragma unroll
            for (int it = 0; it < 8; it++) {
                int l = fr0 + it * 16;
                *(float2*)(d + (l >> 3) * 20 + (l & 7) * 2) = make_float2(wr[it], wr[it]);
            }
        };
        auto compute = [&](int st) {
            const float* xb = As + st * B_ASZ + tb * 8;
            const float* wb = Bs + st * B_WSZ + to * 20;
            #pragma unroll
            for (int kk = 0; kk < 16; kk++) {
                const ulonglong2* xp = (const ulonglong2*)(xb + kk * B_ASTR);
                const ulonglong2* wp = (const ulonglong2*)(wb + kk * B_WSTR);
                ulonglong2 x01 = xp[0], x23 = xp[1];
                ulonglong2 w01 = wp[0], w23 = wp[1], w45 = wp[2], w67 = wp[3];
                u64 xv[4] = {x01.x, x01.y, x23.x, x23.y};
                u64 wv[8] = {w01.x, w01.y, w23.x, w23.y, w45.x, w45.y, w67.x, w67.y};
                #pragma unroll
                for (int i = 0; i < 4; i++)
                    #pragma unroll
                    for (int j = 0; j < 8; j++)
                        acc[i][j] = fma2(xv[i], wv[j], acc[i][j]);
            }
        };

        fillA(0, 0); cp_commit();
        ldgW(0);
        if (nt > 1) fillA(1, 1);
        cp_commit();
        stsW(0);
        if (nt > 1) ldgW(1);
        cp_wait1();
        __syncthreads();

        for (int t = 0; t < nt; t++) {
            int st = t & 1;
            compute(st);
            __syncthreads();
            if (t + 2 < nt) fillA(t + 2, st);
            cp_commit();
            if (t + 1 < nt) stsW(st ^ 1);
            if (t + 2 < nt) ldgW(t + 2);
            cp_wait1();
            __syncthreads();
        }
    }

    #pragma unroll
    for (int j = 0; j < 8; j++) {
        int n = n0 + to * 8 + j;
        if (n < N_REG) {
            #pragma unroll
            for (int i = 0; i < 4; i++) {
                float2 v = unpack2(acc[i][j]);
                int m = m0 + tb * 8 + 2 * i;
                g_partial[((size_t)s * BATCH + m)     * N_REG + n] = v.x;
                g_partial[((size_t)s * BATCH + m + 1) * N_REG + n] = v.y;
            }
        }
    }
}

// ============================================================
// Split-K reduce + bias -> reg_out  (600 CTAs, high MLP)
// ============================================================
__global__ void reg_reduce_kernel(const float* __restrict__ b_reg,
                                  float* __restrict__ reg_out) {
    int i = blockIdx.x * blockDim.x + threadIdx.x;
    if (i >= BATCH * N_REG) return;
    int n = i % N_REG;
    float sum = b_reg[n];
    #pragma unroll
    for (int k = 0; k < SPLITK; k++)
        sum += g_partial[(size_t)k * BATCH * N_REG + i];
    reg_out[i] = sum;
}

// ============================================================
// Stage C: cls GEMV + softmax.  128 CTAs x 4 rows.
// ============================================================
#define C_ROWS 4

__global__ __launch_bounds__(256)
void cls_softmax_kernel(const float* __restrict__ reg_out,
                        const float* __restrict__ W_cls,
                        const float* __restrict__ b_cls,
                        float* __restrict__ y_pred) {
    __shared__ float rows[C_ROWS][304];
    __shared__ float lg[C_ROWS][192];

    const int m0  = blockIdx.x * C_ROWS;
    const int tid = threadIdx.x;

    for (int p = tid; p < C_ROWS * N_REG; p += 256) {
        int mi = p / N_REG, n = p % N_REG;
        rows[mi][n] = reg_out[(size_t)(m0 + mi) * N_REG + n];
    }
    __syncthreads();

    for (int q = tid; q < C_ROWS * N_CLS; q += 256) {
        int mi = q / N_CLS, n = q % N_CLS;
        const float4* w  = (const float4*)(W_cls + (size_t)n * N_REG);
        const float4* rr = (const float4*)rows[mi];
        float s0 = b_cls[n], s1 = 0.f;
        #pragma unroll 5
        for (int k4 = 0; k4 < N_REG / 4; k4++) {
            float4 a = rr[k4];
            float4 b = __ldg(&w[k4]);
            s0 = fmaf(a.x, b.x, s0);
            s1 = fmaf(a.y, b.y, s1);
            s0 = fmaf(a.z, b.z, s0);
            s1 = fmaf(a.w, b.w, s1);
        }
        lg[mi][n] = s0 + s1;
    }
    __syncthreads();

    int w = tid >> 5, lane = tid & 31;
    if (w < C_ROWS) {
        int mi = w;
        float mx = -1e30f;
        for (int n = lane; n < N_CLS; n += 32) mx = fmaxf(mx, lg[mi][n]);
        #pragma unroll
        for (int off = 16; off > 0; off >>= 1)
            mx = fmaxf(mx, __shfl_xor_sync(0xffffffff, mx, off));
        float sum = 0.f;
        for (int n = lane; n < N_CLS; n += 32) {
            float e = expf(lg[mi][n] - mx);
            lg[mi][n] = e;
            sum += e;
        }
        #pragma unroll
        for (int off = 16; off > 0; off >>= 1)
            sum += __shfl_xor_sync(0xffffffff, sum, off);
        float inv = 1.f / sum;
        for (int n = lane; n < N_CLS; n += 32)
            y_pred[(size_t)(m0 + mi) * N_CLS + n] = lg[mi][n] * inv;
    }
}

// ============================================================
// Launch
// ============================================================
extern "C" void kernel_launch(void* const* d_in, const int* in_sizes, int n_in,
                              void* d_out, int out_size) {
    const float* x     = (const float*)d_in[0];
    const float* W_enc = (const float*)d_in[1];
    const float* b_enc = (const float*)d_in[2];
    const float* gamma = (const float*)d_in[3];
    const float* beta  = (const float*)d_in[4];
    const float* rmean = (const float*)d_in[5];
    const float* rvar  = (const float*)d_in[6];
    const float* W_reg = (const float*)d_in[7];
    const float* b_reg = (const float*)d_in[8];
    const float* W_cls = (const float*)d_in[9];
    const float* b_cls = (const float*)d_in[10];
    const int*   idx   = (const int*)d_in[11];
    const int*   srci  = (const int*)d_in[12];

    const int total   = in_sizes[0] / BATCH;
    const int max_out = in_sizes[2] / NUM_ROIS;
    const int max_in  = in_sizes[11] / NUM_ROIS;
    const int C       = in_sizes[12];

    float* out        = (float*)d_out;
    float* concat_out = out;
    float* reg_out    = out + (size_t)BATCH * C;
    float* y_pred     = reg_out + (size_t)BATCH * N_REG;

    cudaFuncSetAttribute(roi_enc_kernel,
                         cudaFuncAttributeMaxDynamicSharedMemorySize, A_SMEM);
    cudaFuncSetAttribute(reg_gemm_kernel,
                         cudaFuncAttributeMaxDynamicSharedMemorySize, B_SMEM);

    setup_kernel<<<1, 512>>>(idx, srci, max_in, max_out, total, C);

    // persistent stage A: one CTA per concurrent slot (2/SM x 148 SMs)
    roi_enc_kernel<<<296, 256, A_SMEM>>>(x, W_enc, b_enc, gamma, beta, rmean, rvar,
                                         concat_out, total, max_in, max_out, C);

    dim3 gB(BATCH / 128, (N_REG + 127) / 128, SPLITK);
    reg_gemm_kernel<<<gB, 256, B_SMEM>>>(concat_out, W_reg, C);

    reg_reduce_kernel<<<(BATCH * N_REG + 255) / 256, 256>>>(b_reg, reg_out);

    cls_softmax_kernel<<<BATCH / C_ROWS, 256>>>(reg_out, W_cls, b_cls, y_pred);
}

// round 12
// speedup vs baseline: 1.5958x; 1.2951x over previous
#include <cuda_runtime.h>
#include <cuda_bf16.h>
#include <cstdint>
#include <math.h>

#define NUM_ROIS 333
#define BATCH    512
#define N_REG    300
#define N_CLS    180
#define EPSV     1e-5f
#define SLOPEV   0.3f
#define SPLITK   24
#define C64MAX   20736
#define WROWS    384

// compile-time feature gate: true only in the sm_103a (arch-specific) pass
#if defined(__CUDA_ARCH__) && (defined(__CUDA_ARCH_FEAT_SM103_ALL) || defined(__CUDA_ARCH_FEAT_SM100_ALL) || defined(__CUDA_ARCH_FEAT_SM101_ALL))
#define HAVE_TC 1
#else
#define HAVE_TC 0
#endif

// -------- static device scratch (no allocations allowed) --------
__device__ int   g_base[NUM_ROIS];
__device__ int   g_size[NUM_ROIS];
__device__ int   g_red [NUM_ROIS];
__device__ int   g_off [NUM_ROIS];
__device__ int   g_order[NUM_ROIS];
__device__ __align__(16) float g_partial[SPLITK * BATCH * N_REG];
__device__ __align__(16) __nv_bfloat16 g_Ah[(size_t)BATCH * C64MAX];
__device__ __align__(16) __nv_bfloat16 g_Al[(size_t)BATCH * C64MAX];
__device__ __align__(16) __nv_bfloat16 g_Wh[(size_t)WROWS * C64MAX];
__device__ __align__(16) __nv_bfloat16 g_Wl[(size_t)WROWS * C64MAX];

typedef unsigned long long u64;

__device__ __forceinline__ u64 fma2(u64 a, u64 b, u64 c) {
    u64 d;
    asm("fma.rn.f32x2 %0, %1, %2, %3;" : "=l"(d) : "l"(a), "l"(b), "l"(c));
    return d;
}
__device__ __forceinline__ float2 unpack2(u64 v) {
    float lo, hi;
    asm("mov.b64 {%0, %1}, %2;" : "=f"(lo), "=f"(hi) : "l"(v));
    return make_float2(lo, hi);
}
__device__ __forceinline__ unsigned sptr(const void* p) {
    return (unsigned)__cvta_generic_to_shared(p);
}
__device__ __forceinline__ void cpa4(unsigned dst, const void* src) {
    asm volatile("cp.async.ca.shared.global [%0], [%1], 4;" :: "r"(dst), "l"(src));
}
__device__ __forceinline__ void cp16(unsigned dst, const void* src) {
    asm volatile("cp.async.cg.shared.global [%0], [%1], 16;" :: "r"(dst), "l"(src));
}
__device__ __forceinline__ void cp_commit() { asm volatile("cp.async.commit_group;"); }
__device__ __forceinline__ void cp_wait1()  { asm volatile("cp.async.wait_group 1;" ::: "memory"); }

// ============================================================
// Setup: per-ROI meta + size-descending schedule
// ============================================================
__global__ void setup_kernel(const int* __restrict__ idx,
                             const int* __restrict__ src_index,
                             int max_in, int max_out, int total, int C) {
    int t = threadIdx.x;
    __shared__ int s_size[NUM_ROIS];
    for (int r = t; r < NUM_ROIS; r += blockDim.x) {
        const int* row = idx + (size_t)r * max_in;
        int lo = 0, hi = max_in;
        while (lo < hi) {
            int mid = (lo + hi) >> 1;
            if (row[mid] == total) hi = mid; else lo = mid + 1;
        }
        g_size[r] = lo;
        s_size[r] = lo;
        g_base[r] = row[0];
    }
    __shared__ int cnt[NUM_ROIS];
    for (int r = t; r < NUM_ROIS; r += blockDim.x) cnt[r] = 0;
    __syncthreads();
    for (int p = t; p < C; p += blockDim.x)
        atomicAdd(&cnt[src_index[p] / max_out], 1);
    __syncthreads();
    if (t == 0) {
        int off = 0;
        for (int r = 0; r < NUM_ROIS; r++) {
            g_red[r] = cnt[r];
            g_off[r] = off;
            off += cnt[r];
        }
    }
    __syncthreads();
    for (int r = t; r < NUM_ROIS; r += blockDim.x) {
        int sz = s_size[r];
        int rank = 0;
        for (int j = 0; j < NUM_ROIS; j++) {
            int sj = s_size[j];
            if (sj > sz || (sj == sz && j < r)) rank++;
        }
        g_order[rank] = r;
    }
}

// ============================================================
// Stage A: per-ROI GEMM (256 batch x 32 out) + BN + leaky -> concat_out
// (exactly the R7 / 445us version)
// ============================================================
#define A_XSTR 260
#define A_WSTR 100
#define A_XSZ  (16 * A_XSTR)
#define A_WSZ  (16 * A_WSTR)
#define A_SMEM ((2 * A_XSZ + 2 * A_WSZ) * 4)

__global__ __launch_bounds__(256, 2)
void roi_enc_kernel(const float* __restrict__ x, const float* __restrict__ W_enc,
                    const float* __restrict__ b_enc, const float* __restrict__ gamma,
                    const float* __restrict__ beta, const float* __restrict__ rmean,
                    const float* __restrict__ rvar, float* __restrict__ concat_out,
                    int total, int max_in, int max_out, int C)
{
    extern __shared__ float sm[];
    float* Xs = sm;
    float* Ws = sm + 2 * A_XSZ;

    const int r    = g_order[blockIdx.x];
    const int b0   = blockIdx.y * 256;
    const int ot   = blockIdx.z * 32;
    const int size = g_size[r];
    const int red  = g_red[r];
    const int base = g_base[r];
    const int ooff = g_off[r];
    if (ot >= red) return;

    const int tid = threadIdx.x;
    const int tb  = tid >> 3;
    const int to  = tid & 7;
    const int fk  = tid & 15;
    const int fr0 = tid >> 4;

    const float* xg = x + (size_t)b0 * total + base;
    const float* wg = W_enc + (size_t)r * max_out * max_in;
    const unsigned xs_u = sptr(Xs);

    const int nt = (size + 15) >> 4;

    u64 acc[4][4];
    #pragma unroll
    for (int i = 0; i < 4; i++)
        #pragma unroll
        for (int j = 0; j < 4; j++) acc[i][j] = 0ull;

    float wr[2];

    auto fillX = [&](int t, int st) {
        int kg = t * 16 + fk;
        if (kg < size) {
            const float* src = xg + kg;
            unsigned dst = xs_u + (unsigned)(st * A_XSZ + fk * A_XSTR) * 4u;
            #pragma unroll
            for (int it = 0; it < 16; it++) {
                int b = fr0 + it * 16;
                cpa4(dst + (unsigned)b * 4u, src + (size_t)b * total);
            }
        } else {
            float* d = Xs + st * A_XSZ + fk * A_XSTR;
            #pragma unroll
            for (int it = 0; it < 16; it++) d[fr0 + it * 16] = 0.f;
        }
    };
    auto ldgW = [&](int t) {
        int kg = t * 16 + fk;
        #pragma unroll
        for (int it = 0; it < 2; it++) {
            int o = ot + fr0 + it * 16;
            wr[it] = (o < max_out && kg < size) ? wg[(size_t)o * max_in + kg] : 0.f;
        }
    };
    auto stsW = [&](int st) {
        float* d = Ws + st * A_WSZ + fk * A_WSTR;
        #pragma unroll
        for (int it = 0; it < 2; it++) {
            int o = fr0 + it * 16;
            *(float2*)(d + (o >> 2) * 12 + (o & 3) * 2) = make_float2(wr[it], wr[it]);
        }
    };
    auto compute = [&](int st) {
        const float* xb = Xs + st * A_XSZ + tb * 8;
        const float* wb = Ws + st * A_WSZ + to * 12;
        #pragma unroll
        for (int kk = 0; kk < 16; kk++) {
            const ulonglong2* xp = (const ulonglong2*)(xb + kk * A_XSTR);
            const ulonglong2* wp = (const ulonglong2*)(wb + kk * A_WSTR);
            ulonglong2 x01 = xp[0], x23 = xp[1];
            ulonglong2 w01 = wp[0], w23 = wp[1];
            u64 xv[4] = {x01.x, x01.y, x23.x, x23.y};
            u64 wv[4] = {w01.x, w01.y, w23.x, w23.y};
            #pragma unroll
            for (int i = 0; i < 4; i++)
                #pragma unroll
                for (int j = 0; j < 4; j++)
                    acc[i][j] = fma2(xv[i], wv[j], acc[i][j]);
        }
    };

    fillX(0, 0); cp_commit();
    ldgW(0);
    if (nt > 1) fillX(1, 1);
    cp_commit();
    stsW(0);
    if (nt > 1) ldgW(1);
    cp_wait1();
    __syncthreads();

    for (int t = 0; t < nt; t++) {
        int st = t & 1;
        compute(st);
        __syncthreads();
        if (t + 2 < nt) fillX(t + 2, st);
        cp_commit();
        if (t + 1 < nt) stsW(st ^ 1);
        if (t + 2 < nt) ldgW(t + 2);
        cp_wait1();
        __syncthreads();
    }

    float* Ysm = sm;
    for (int half = 0; half < 2; half++) {
        __syncthreads();
        if ((tb >> 4) == half) {
            int bl = (tb & 15) * 8;
            #pragma unroll
            for (int jj = 0; jj < 4; jj++) {
                int og = ot + to * 4 + jj;
                if (og < red) {
                    size_t po = (size_t)r * max_out + og;
                    float be  = b_enc[po];
                    float ga  = gamma[po];
                    float bt  = beta[po];
                    float mn  = rmean[po];
                    float inv = rsqrtf(rvar[po] + EPSV);
                    int ol = to * 4 + jj;
                    #pragma unroll
                    for (int i = 0; i < 4; i++) {
                        float2 v = unpack2(acc[i][jj]);
                        float y0 = ga * (v.x + be - mn) * inv + bt;
                        float y1 = ga * (v.y + be - mn) * inv + bt;
                        y0 = (y0 > 0.f) ? y0 : SLOPEV * y0;
                        y1 = (y1 > 0.f) ? y1 : SLOPEV * y1;
                        Ysm[(bl + 2 * i)     * 33 + ol] = y0;
                        Ysm[(bl + 2 * i + 1) * 33 + ol] = y1;
                    }
                }
            }
        }
        __syncthreads();
        for (int p = tid; p < 128 * 32; p += 256) {
            int bl = p >> 5, o = p & 31;
            int og = ot + o;
            if (og < red)
                concat_out[(size_t)(b0 + half * 128 + bl) * C + ooff + og] =
                    Ysm[bl * 33 + o];
        }
    }
}

// ============================================================
// bf16 hi/lo split conversion (A: which=0, W: which=1) — TC path only
// ============================================================
__global__ void conv_pair_kernel(const float* __restrict__ src, int which,
                                 int rows_valid, int C, int C64, int rows_total)
{
#if HAVE_TC
    size_t i = (size_t)blockIdx.x * blockDim.x + threadIdx.x;
    size_t npairs = (size_t)rows_total * C64 / 2;
    if (i >= npairs) return;
    int halfC = C64 >> 1;
    int m = (int)(i / halfC);
    int k = (int)(i - (size_t)m * halfC) * 2;
    float v0 = 0.f, v1 = 0.f;
    if (m < rows_valid) {
        if (k     < C) v0 = src[(size_t)m * C + k];
        if (k + 1 < C) v1 = src[(size_t)m * C + k + 1];
    }
    __nv_bfloat16 h0 = __float2bfloat16(v0);
    __nv_bfloat16 h1 = __float2bfloat16(v1);
    __nv_bfloat162 hp; hp.x = h0; hp.y = h1;
    __nv_bfloat162 lp;
    lp.x = __float2bfloat16(v0 - __bfloat162float(h0));
    lp.y = __float2bfloat16(v1 - __bfloat162float(h1));
    if (which == 0) {
        ((__nv_bfloat162*)g_Ah)[i] = hp;
        ((__nv_bfloat162*)g_Al)[i] = lp;
    } else {
        ((__nv_bfloat162*)g_Wh)[i] = hp;
        ((__nv_bfloat162*)g_Wl)[i] = lp;
    }
#endif
}

// ============================================================
// Stage B (TC path): tcgen05 bf16-split GEMM -> g_partial (split-K)
// ============================================================
#define TC_TILE 16384
#define TC_SMEM (1024 + 8 * TC_TILE)

__global__ __launch_bounds__(128, 1)
void reg_gemm_tc(int C64)
{
#if HAVE_TC
    extern __shared__ char smem[];
    const unsigned sbase = sptr(smem);
    const int tid = threadIdx.x, wid = tid >> 5, lane = tid & 31;
    const int m0 = blockIdx.x * 128, n0 = blockIdx.y * 128, s = blockIdx.z;

    const int ktiles = C64 >> 6;
    const int chunk  = (ktiles + SPLITK - 1) / SPLITK;
    const int t0 = s * chunk;
    const int nt = max(0, min(ktiles, t0 + chunk) - t0);

    if (wid == 0)
        asm volatile("tcgen05.alloc.cta_group::1.sync.aligned.shared::cta.b32 [%0], %1;"
                     :: "r"(sbase), "r"(128u) : "memory");
    __syncthreads();
    uint32_t tmem;
    asm volatile("ld.shared.b32 %0, [%1];" : "=r"(tmem) : "r"(sbase));
    if (tid == 0)
        asm volatile("mbarrier.init.shared.b64 [%0], %1;" :: "r"(sbase + 8), "r"(1u) : "memory");
    __syncthreads();

    auto fill = [&](int kt, int st) {
        const size_t kb = (size_t)kt << 6;
        const unsigned ba = sbase + 1024 + (unsigned)(st * 4) * TC_TILE;
        const int c = tid & 7;
        #pragma unroll
        for (int p = 0; p < 8; p++) {
            int row = p * 16 + (tid >> 3);
            unsigned off = (unsigned)(row * 128 + c * 16);
            unsigned sw = off ^ ((off >> 3) & 0x70);
            size_t aoff = (size_t)(m0 + row) * C64 + kb + c * 8;
            size_t woff = (size_t)(n0 + row) * C64 + kb + c * 8;
            cp16(ba + sw,               g_Ah + aoff);
            cp16(ba + TC_TILE     + sw, g_Al + aoff);
            cp16(ba + 2 * TC_TILE + sw, g_Wh + woff);
            cp16(ba + 3 * TC_TILE + sw, g_Wl + woff);
        }
    };

    // idesc: dtype=F32, atype=btype=BF16, N=128 (16<<17), M=128 (8<<24)
    const uint32_t idesc = (8u << 24) | (16u << 17) | (1u << 10) | (1u << 7) | (1u << 4);
    const uint64_t DBASE = (2ull << 61) | (1ull << 46) | (64ull << 32) | (1ull << 16);

    if (nt > 0) {
        fill(t0, 0); cp_commit();
        if (nt > 1) fill(t0 + 1, 1);
        cp_commit();
        for (int t = 0; t < nt; t++) {
            const int st = t & 1;
            cp_wait1();
            asm volatile("fence.proxy.async.shared::cta;" ::: "memory");
            __syncthreads();
            uint32_t is_el;
            asm volatile("{\n\t.reg .pred p;\n\telect.sync _|p, 0xFFFFFFFF;\n\t"
                         "selp.b32 %0, 1, 0, p;\n\t}" : "=r"(is_el));
            if (wid == 0 && is_el) {
                const unsigned ba = sbase + 1024 + (unsigned)(st * 4) * TC_TILE;
                uint64_t ah = DBASE | ((uint64_t)(ba >> 4) & 0x3FFF);
                uint64_t al = DBASE | ((uint64_t)((ba + TC_TILE) >> 4) & 0x3FFF);
                uint64_t bh = DBASE | ((uint64_t)((ba + 2 * TC_TILE) >> 4) & 0x3FFF);
                uint64_t bl = DBASE | ((uint64_t)((ba + 3 * TC_TILE) >> 4) & 0x3FFF);
                #pragma unroll
                for (int kk = 0; kk < 4; kk++) {
                    uint32_t en0 = (t > 0 || kk > 0) ? 1u : 0u;
                    asm volatile("{\n\t.reg .pred p;\n\tsetp.ne.u32 p, %5, 0;\n\t"
                                 "tcgen05.mma.cta_group::1.kind::f16 [%0], %1, %2, %3, {%4,%4,%4,%4}, p;\n\t}"
                                 :: "r"(tmem), "l"(ah + kk * 2), "l"(bh + kk * 2),
                                    "r"(idesc), "r"(0u), "r"(en0) : "memory");
                    asm volatile("{\n\t.reg .pred p;\n\tsetp.ne.u32 p, %5, 0;\n\t"
                                 "tcgen05.mma.cta_group::1.kind::f16 [%0], %1, %2, %3, {%4,%4,%4,%4}, p;\n\t}"
                                 :: "r"(tmem), "l"(ah + kk * 2), "l"(bl + kk * 2),
                                    "r"(idesc), "r"(0u), "r"(1u) : "memory");
                    asm volatile("{\n\t.reg .pred p;\n\tsetp.ne.u32 p, %5, 0;\n\t"
                                 "tcgen05.mma.cta_group::1.kind::f16 [%0], %1, %2, %3, {%4,%4,%4,%4}, p;\n\t}"
                                 :: "r"(tmem), "l"(al + kk * 2), "l"(bh + kk * 2),
                                    "r"(idesc), "r"(0u), "r"(1u) : "memory");
                }
                asm volatile("tcgen05.commit.cta_group::1.mbarrier::arrive::one.shared::cluster.b64 [%0];"
                             :: "r"(sbase + 8) : "memory");
            }
            {
                uint32_t par = (uint32_t)(t & 1);
                asm volatile("{\n\t.reg .pred P;\n\t"
                             "WL_%=:\n\t"
                             "mbarrier.try_wait.parity.acquire.cta.shared::cta.b64 P, [%0], %1, 0x989680;\n\t"
                             "@P bra.uni WD_%=;\n\t"
                             "bra.uni WL_%=;\n\t"
                             "WD_%=:\n\t}" :: "r"(sbase + 8), "r"(par) : "memory");
            }
            if (t + 2 < nt) fill(t0 + t + 2, st);
            cp_commit();
        }
        asm volatile("tcgen05.fence::after_thread_sync;" ::: "memory");
    }
    __syncthreads();

    // epilogue: TMEM -> g_partial (zeros if this split had no work)
    {
        const int m = m0 + wid * 32 + lane;
        float* drow = g_partial + ((size_t)s * BATCH + m) * N_REG;
        for (int c0 = 0; c0 < 128; c0 += 32) {
            uint32_t r[32];
            if (nt > 0) {
                asm volatile(
                    "tcgen05.ld.sync.aligned.32x32b.x32.b32 "
                    "{%0, %1, %2, %3, %4, %5, %6, %7, "
                    " %8, %9, %10, %11, %12, %13, %14, %15, "
                    " %16, %17, %18, %19, %20, %21, %22, %23, "
                    " %24, %25, %26, %27, %28, %29, %30, %31}, [%32];"
                    : "=r"(r[0]),  "=r"(r[1]),  "=r"(r[2]),  "=r"(r[3]),
                      "=r"(r[4]),  "=r"(r[5]),  "=r"(r[6]),  "=r"(r[7]),
                      "=r"(r[8]),  "=r"(r[9]),  "=r"(r[10]), "=r"(r[11]),
                      "=r"(r[12]), "=r"(r[13]), "=r"(r[14]), "=r"(r[15]),
                      "=r"(r[16]), "=r"(r[17]), "=r"(r[18]), "=r"(r[19]),
                      "=r"(r[20]), "=r"(r[21]), "=r"(r[22]), "=r"(r[23]),
                      "=r"(r[24]), "=r"(r[25]), "=r"(r[26]), "=r"(r[27]),
                      "=r"(r[28]), "=r"(r[29]), "=r"(r[30]), "=r"(r[31])
                    : "r"(tmem + c0));
                asm volatile("tcgen05.wait::ld.sync.aligned;" ::: "memory");
            } else {
                #pragma unroll
                for (int q = 0; q < 32; q++) r[q] = 0u;
            }
            #pragma unroll
            for (int q = 0; q < 8; q++) {
                int n = n0 + c0 + q * 4;
                if (n + 3 < N_REG) {
                    *(float4*)(drow + n) = make_float4(
                        __uint_as_float(r[q * 4]),     __uint_as_float(r[q * 4 + 1]),
                        __uint_as_float(r[q * 4 + 2]), __uint_as_float(r[q * 4 + 3]));
                } else {
                    #pragma unroll
                    for (int j = 0; j < 4; j++)
                        if (n + j < N_REG) drow[n + j] = __uint_as_float(r[q * 4 + j]);
                }
            }
        }
    }
    __syncthreads();
    if (wid == 0)
        asm volatile("tcgen05.dealloc.cta_group::1.sync.aligned.b32 %0, %1;"
                     :: "r"(tmem), "r"(128u));
#endif
}

// ============================================================
// Stage B (fallback path): R7 FFMA2 GEMM -> g_partial (split-K)
// Active only when the tensor path is compiled out.
// ============================================================
#define B_ASTR 132
#define B_WSTR 324
#define B_ASZ  (16 * B_ASTR)
#define B_WSZ  (16 * B_WSTR)
#define B_SMEM ((2 * B_ASZ + 2 * B_WSZ) * 4)

__global__ __launch_bounds__(256, 2)
void reg_gemm_kernel(const float* __restrict__ A, const float* __restrict__ Wr, int C)
{
#if HAVE_TC
    return;   // tensor path handles stage B in this cubin
#else
    extern __shared__ float sm[];
    float* As = sm;
    float* Bs = sm + 2 * B_ASZ;

    const int m0 = blockIdx.x * 128;
    const int n0 = blockIdx.y * 128;
    const int s  = blockIdx.z;
    const int chunk = (C + SPLITK - 1) / SPLITK;
    const int kbeg  = s * chunk;
    const int kend  = min(C, kbeg + chunk);
    const int klen  = kend - kbeg;

    const int tid = threadIdx.x;
    const int tb  = tid >> 4;
    const int to  = tid & 15;
    const int fk  = tid & 15;
    const int fr0 = tid >> 4;

    const unsigned as_u = sptr(As);

    u64 acc[4][8];
    #pragma unroll
    for (int i = 0; i < 4; i++)
        #pragma unroll
        for (int j = 0; j < 8; j++) acc[i][j] = 0ull;

    if (klen > 0) {
        const int nt = (klen + 15) >> 4;
        float wr[8];

        auto fillA = [&](int t, int st) {
            int kg = kbeg + t * 16 + fk;
            if (kg < kend) {
                unsigned dst = as_u + (unsigned)(st * B_ASZ + fk * B_ASTR) * 4u;
                const float* src = A + kg;
                #pragma unroll
                for (int it = 0; it < 8; it++) {
                    int m = fr0 + it * 16;
                    cpa4(dst + (unsigned)m * 4u, src + (size_t)(m0 + m) * C);
                }
            } else {
                float* d = As + st * B_ASZ + fk * B_ASTR;
                #pragma unroll
                for (int it = 0; it < 8; it++) d[fr0 + it * 16] = 0.f;
            }
        };
        auto ldgW = [&](int t) {
            int kg = kbeg + t * 16 + fk;
            #pragma unroll
            for (int it = 0; it < 8; it++) {
                int n = n0 + fr0 + it * 16;
                wr[it] = (n < N_REG && kg < kend) ? Wr[(size_t)n * C + kg] : 0.f;
            }
        };
        auto stsW = [&](int st) {
            float* d = Bs + st * B_WSZ + fk * B_WSTR;
            #pragma unroll
            for (int it = 0; it < 8; it++) {
                int l = fr0 + it * 16;
                *(float2*)(d + (l >> 3) * 20 + (l & 7) * 2) = make_float2(wr[it], wr[it]);
            }
        };
        auto compute = [&](int st) {
            const float* xb = As + st * B_ASZ + tb * 8;
            const float* wb = Bs + st * B_WSZ + to * 20;
            #pragma unroll
            for (int kk = 0; kk < 16; kk++) {
                const ulonglong2* xp = (const ulonglong2*)(xb + kk * B_ASTR);
                const ulonglong2* wp = (const ulonglong2*)(wb + kk * B_WSTR);
                ulonglong2 x01 = xp[0], x23 = xp[1];
                ulonglong2 w01 = wp[0], w23 = wp[1], w45 = wp[2], w67 = wp[3];
                u64 xv[4] = {x01.x, x01.y, x23.x, x23.y};
                u64 wv[8] = {w01.x, w01.y, w23.x, w23.y, w45.x, w45.y, w67.x, w67.y};
                #pragma unroll
                for (int i = 0; i < 4; i++)
                    #pragma unroll
                    for (int j = 0; j < 8; j++)
                        acc[i][j] = fma2(xv[i], wv[j], acc[i][j]);
            }
        };

        fillA(0, 0); cp_commit();
        ldgW(0);
        if (nt > 1) fillA(1, 1);
        cp_commit();
        stsW(0);
        if (nt > 1) ldgW(1);
        cp_wait1();
        __syncthreads();

        for (int t = 0; t < nt; t++) {
            int st = t & 1;
            compute(st);
            __syncthreads();
            if (t + 2 < nt) fillA(t + 2, st);
            cp_commit();
            if (t + 1 < nt) stsW(st ^ 1);
            if (t + 2 < nt) ldgW(t + 2);
            cp_wait1();
            __syncthreads();
        }
    }

    #pragma unroll
    for (int j = 0; j < 8; j++) {
        int n = n0 + to * 8 + j;
        if (n < N_REG) {
            #pragma unroll
            for (int i = 0; i < 4; i++) {
                float2 v = unpack2(acc[i][j]);
                int m = m0 + tb * 8 + 2 * i;
                g_partial[((size_t)s * BATCH + m)     * N_REG + n] = v.x;
                g_partial[((size_t)s * BATCH + m + 1) * N_REG + n] = v.y;
            }
        }
    }
#endif
}

// ============================================================
// Split-K reduce + bias -> reg_out
// ============================================================
__global__ void reg_reduce_kernel(const float* __restrict__ b_reg,
                                  float* __restrict__ reg_out) {
    int i = blockIdx.x * blockDim.x + threadIdx.x;
    if (i >= BATCH * N_REG) return;
    int n = i % N_REG;
    float sum = b_reg[n];
    #pragma unroll
    for (int k = 0; k < SPLITK; k++)
        sum += g_partial[(size_t)k * BATCH * N_REG + i];
    reg_out[i] = sum;
}

// ============================================================
// Stage C: cls GEMV + softmax.  128 CTAs x 4 rows.
// ============================================================
#define C_ROWS 4

__global__ __launch_bounds__(256)
void cls_softmax_kernel(const float* __restrict__ reg_out,
                        const float* __restrict__ W_cls,
                        const float* __restrict__ b_cls,
                        float* __restrict__ y_pred) {
    __shared__ float rows[C_ROWS][304];
    __shared__ float lg[C_ROWS][192];

    const int m0  = blockIdx.x * C_ROWS;
    const int tid = threadIdx.x;

    for (int p = tid; p < C_ROWS * N_REG; p += 256) {
        int mi = p / N_REG, n = p % N_REG;
        rows[mi][n] = reg_out[(size_t)(m0 + mi) * N_REG + n];
    }
    __syncthreads();

    for (int q = tid; q < C_ROWS * N_CLS; q += 256) {
        int mi = q / N_CLS, n = q % N_CLS;
        const float4* w  = (const float4*)(W_cls + (size_t)n * N_REG);
        const float4* rr = (const float4*)rows[mi];
        float s0 = b_cls[n], s1 = 0.f;
        #pragma unroll 5
        for (int k4 = 0; k4 < N_REG / 4; k4++) {
            float4 a = rr[k4];
            float4 b = __ldg(&w[k4]);
            s0 = fmaf(a.x, b.x, s0);
            s1 = fmaf(a.y, b.y, s1);
            s0 = fmaf(a.z, b.z, s0);
            s1 = fmaf(a.w, b.w, s1);
        }
        lg[mi][n] = s0 + s1;
    }
    __syncthreads();

    int w = tid >> 5, lane = tid & 31;
    if (w < C_ROWS) {
        int mi = w;
        float mx = -1e30f;
        for (int n = lane; n < N_CLS; n += 32) mx = fmaxf(mx, lg[mi][n]);
        #pragma unroll
        for (int off = 16; off > 0; off >>= 1)
            mx = fmaxf(mx, __shfl_xor_sync(0xffffffff, mx, off));
        float sum = 0.f;
        for (int n = lane; n < N_CLS; n += 32) {
            float e = expf(lg[mi][n] - mx);
            lg[mi][n] = e;
            sum += e;
        }
        #pragma unroll
        for (int off = 16; off > 0; off >>= 1)
            sum += __shfl_xor_sync(0xffffffff, sum, off);
        float inv = 1.f / sum;
        for (int n = lane; n < N_CLS; n += 32)
            y_pred[(size_t)(m0 + mi) * N_CLS + n] = lg[mi][n] * inv;
    }
}

// ============================================================
// Launch
// ============================================================
extern "C" void kernel_launch(void* const* d_in, const int* in_sizes, int n_in,
                              void* d_out, int out_size) {
    const float* x     = (const float*)d_in[0];
    const float* W_enc = (const float*)d_in[1];
    const float* b_enc = (const float*)d_in[2];
    const float* gamma = (const float*)d_in[3];
    const float* beta  = (const float*)d_in[4];
    const float* rmean = (const float*)d_in[5];
    const float* rvar  = (const float*)d_in[6];
    const float* W_reg = (const float*)d_in[7];
    const float* b_reg = (const float*)d_in[8];
    const float* W_cls = (const float*)d_in[9];
    const float* b_cls = (const float*)d_in[10];
    const int*   idx   = (const int*)d_in[11];
    const int*   srci  = (const int*)d_in[12];

    const int total   = in_sizes[0] / BATCH;
    const int max_out = in_sizes[2] / NUM_ROIS;
    const int max_in  = in_sizes[11] / NUM_ROIS;
    const int C       = in_sizes[12];
    const int C64     = ((C + 63) / 64) * 64;

    float* out        = (float*)d_out;
    float* concat_out = out;
    float* reg_out    = out + (size_t)BATCH * C;
    float* y_pred     = reg_out + (size_t)BATCH * N_REG;

    cudaFuncSetAttribute(roi_enc_kernel,
                         cudaFuncAttributeMaxDynamicSharedMemorySize, A_SMEM);
    cudaFuncSetAttribute(reg_gemm_tc,
                         cudaFuncAttributeMaxDynamicSharedMemorySize, TC_SMEM);
    cudaFuncSetAttribute(reg_gemm_kernel,
                         cudaFuncAttributeMaxDynamicSharedMemorySize, B_SMEM);

    setup_kernel<<<1, 512>>>(idx, srci, max_in, max_out, total, C);

    // W conversion (no-op in fallback cubin)
    {
        size_t npairs = (size_t)WROWS * C64 / 2;
        conv_pair_kernel<<<(int)((npairs + 255) / 256), 256>>>(W_reg, 1, N_REG, C, C64, WROWS);
    }

    dim3 gA(NUM_ROIS, BATCH / 256, 2);
    roi_enc_kernel<<<gA, 256, A_SMEM>>>(x, W_enc, b_enc, gamma, beta, rmean, rvar,
                                        concat_out, total, max_in, max_out, C);

    // A conversion (no-op in fallback cubin)
    {
        size_t npairs = (size_t)BATCH * C64 / 2;
        conv_pair_kernel<<<(int)((npairs + 255) / 256), 256>>>(concat_out, 0, BATCH, C, C64, BATCH);
    }

    // both stage-B kernels launch; exactly one does work per cubin
    dim3 gTC(BATCH / 128, 3, SPLITK);
    reg_gemm_tc<<<gTC, 128, TC_SMEM>>>(C64);

    dim3 gB(BATCH / 128, (N_REG + 127) / 128, SPLITK);
    reg_gemm_kernel<<<gB, 256, B_SMEM>>>(concat_out, W_reg, C);

    reg_reduce_kernel<<<(BATCH * N_REG + 255) / 256, 256>>>(b_reg, reg_out);

    cls_softmax_kernel<<<BATCH / C_ROWS, 256>>>(reg_out, W_cls, b_cls, y_pred);
}

// round 14
// speedup vs baseline: 2.2900x; 1.4350x over previous
#include <cuda_runtime.h>
#include <cuda_bf16.h>
#include <cstdint>
#include <math.h>

#define NUM_ROIS 333
#define BATCH    512
#define N_REG    300
#define N_CLS    180
#define EPSV     1e-5f
#define SLOPEV   0.3f
#define SPLITK   24
#define C64MAX   20736
#define WROWS    384

// compile-time feature gate: true only in the sm_103a (arch-specific) pass
#if defined(__CUDA_ARCH__) && (defined(__CUDA_ARCH_FEAT_SM103_ALL) || defined(__CUDA_ARCH_FEAT_SM100_ALL) || defined(__CUDA_ARCH_FEAT_SM101_ALL))
#define HAVE_TC 1
#else
#define HAVE_TC 0
#endif

// -------- static device scratch (no allocations allowed) --------
__device__ int   g_base[NUM_ROIS];
__device__ int   g_size[NUM_ROIS];
__device__ int   g_red [NUM_ROIS];
__device__ int   g_off [NUM_ROIS];
__device__ int   g_order[NUM_ROIS];
__device__ __align__(16) float g_partial[SPLITK * BATCH * N_REG];
__device__ __align__(16) __nv_bfloat16 g_Ah[(size_t)BATCH * C64MAX];
__device__ __align__(16) __nv_bfloat16 g_Al[(size_t)BATCH * C64MAX];
__device__ __align__(16) __nv_bfloat16 g_Wh[(size_t)WROWS * C64MAX];
__device__ __align__(16) __nv_bfloat16 g_Wl[(size_t)WROWS * C64MAX];

typedef unsigned long long u64;

__device__ __forceinline__ u64 fma2(u64 a, u64 b, u64 c) {
    u64 d;
    asm("fma.rn.f32x2 %0, %1, %2, %3;" : "=l"(d) : "l"(a), "l"(b), "l"(c));
    return d;
}
__device__ __forceinline__ float2 unpack2(u64 v) {
    float lo, hi;
    asm("mov.b64 {%0, %1}, %2;" : "=f"(lo), "=f"(hi) : "l"(v));
    return make_float2(lo, hi);
}
__device__ __forceinline__ unsigned sptr(const void* p) {
    return (unsigned)__cvta_generic_to_shared(p);
}
__device__ __forceinline__ void cpa4(unsigned dst, const void* src) {
    asm volatile("cp.async.ca.shared.global [%0], [%1], 4;" :: "r"(dst), "l"(src));
}
__device__ __forceinline__ void cp16(unsigned dst, const void* src) {
    asm volatile("cp.async.cg.shared.global [%0], [%1], 16;" :: "r"(dst), "l"(src));
}
__device__ __forceinline__ void cp_commit() { asm volatile("cp.async.commit_group;"); }
__device__ __forceinline__ void cp_wait1()  { asm volatile("cp.async.wait_group 1;" ::: "memory"); }
__device__ __forceinline__ void cp_wait0()  { asm volatile("cp.async.wait_group 0;" ::: "memory"); }

#if HAVE_TC
__device__ __forceinline__ uint32_t elect1() {
    uint32_t p;
    asm volatile("{\n\t.reg .pred p;\n\telect.sync _|p, 0xFFFFFFFF;\n\t"
                 "selp.b32 %0, 1, 0, p;\n\t}" : "=r"(p));
    return p;
}
__device__ __forceinline__ void mbar_init(uint32_t a, uint32_t cnt) {
    asm volatile("mbarrier.init.shared.b64 [%0], %1;" :: "r"(a), "r"(cnt) : "memory");
}
__device__ __forceinline__ void mbar_wait(uint32_t a, uint32_t parity) {
    asm volatile("{\n\t.reg .pred P;\n\t"
                 "WL_%=:\n\t"
                 "mbarrier.try_wait.parity.acquire.cta.shared::cta.b64 P, [%0], %1, 0x989680;\n\t"
                 "@P bra.uni WD_%=;\n\t"
                 "bra.uni WL_%=;\n\t"
                 "WD_%=:\n\t}" :: "r"(a), "r"(parity) : "memory");
}
__device__ __forceinline__ void mma_bf16_ss(uint32_t d, uint64_t a, uint64_t b,
                                            uint32_t idesc, uint32_t en) {
    asm volatile("{\n\t.reg .pred p;\n\tsetp.ne.u32 p, %5, 0;\n\t"
                 "tcgen05.mma.cta_group::1.kind::f16 [%0], %1, %2, %3, {%4,%4,%4,%4}, p;\n\t}"
                 :: "r"(d), "l"(a), "l"(b), "r"(idesc), "r"(0u), "r"(en) : "memory");
}
__device__ __forceinline__ void tc_commit(uint32_t mbar) {
    asm volatile("tcgen05.commit.cta_group::1.mbarrier::arrive::one.shared::cluster.b64 [%0];"
                 :: "r"(mbar) : "memory");
}
__device__ __forceinline__ void tc_ldx32(uint32_t* r, uint32_t a) {
    asm volatile(
        "tcgen05.ld.sync.aligned.32x32b.x32.b32 "
        "{%0, %1, %2, %3, %4, %5, %6, %7, "
        " %8, %9, %10, %11, %12, %13, %14, %15, "
        " %16, %17, %18, %19, %20, %21, %22, %23, "
        " %24, %25, %26, %27, %28, %29, %30, %31}, [%32];"
        : "=r"(r[0]),  "=r"(r[1]),  "=r"(r[2]),  "=r"(r[3]),
          "=r"(r[4]),  "=r"(r[5]),  "=r"(r[6]),  "=r"(r[7]),
          "=r"(r[8]),  "=r"(r[9]),  "=r"(r[10]), "=r"(r[11]),
          "=r"(r[12]), "=r"(r[13]), "=r"(r[14]), "=r"(r[15]),
          "=r"(r[16]), "=r"(r[17]), "=r"(r[18]), "=r"(r[19]),
          "=r"(r[20]), "=r"(r[21]), "=r"(r[22]), "=r"(r[23]),
          "=r"(r[24]), "=r"(r[25]), "=r"(r[26]), "=r"(r[27]),
          "=r"(r[28]), "=r"(r[29]), "=r"(r[30]), "=r"(r[31])
        : "r"(a));
}
__device__ __forceinline__ uint32_t bf16pack(float v0, float v1,
                                             float& rem0, float& rem1) {
    __nv_bfloat16 h0 = __float2bfloat16(v0);
    __nv_bfloat16 h1 = __float2bfloat16(v1);
    rem0 = v0 - __bfloat162float(h0);
    rem1 = v1 - __bfloat162float(h1);
    __nv_bfloat162 hp; hp.x = h0; hp.y = h1;
    return *reinterpret_cast<uint32_t*>(&hp);
}
__device__ __forceinline__ uint32_t bf16pack2(float v0, float v1) {
    __nv_bfloat162 hp;
    hp.x = __float2bfloat16(v0);
    hp.y = __float2bfloat16(v1);
    return *reinterpret_cast<uint32_t*>(&hp);
}
#endif

// ============================================================
// Setup: per-ROI meta + size-descending schedule
// ============================================================
__global__ void setup_kernel(const int* __restrict__ idx,
                             const int* __restrict__ src_index,
                             int max_in, int max_out, int total, int C) {
    int t = threadIdx.x;
    __shared__ int s_size[NUM_ROIS];
    for (int r = t; r < NUM_ROIS; r += blockDim.x) {
        const int* row = idx + (size_t)r * max_in;
        int lo = 0, hi = max_in;
        while (lo < hi) {
            int mid = (lo + hi) >> 1;
            if (row[mid] == total) hi = mid; else lo = mid + 1;
        }
        g_size[r] = lo;
        s_size[r] = lo;
        g_base[r] = row[0];
    }
    __shared__ int cnt[NUM_ROIS];
    for (int r = t; r < NUM_ROIS; r += blockDim.x) cnt[r] = 0;
    __syncthreads();
    for (int p = t; p < C; p += blockDim.x)
        atomicAdd(&cnt[src_index[p] / max_out], 1);
    __syncthreads();
    if (t == 0) {
        int off = 0;
        for (int r = 0; r < NUM_ROIS; r++) {
            g_red[r] = cnt[r];
            g_off[r] = off;
            off += cnt[r];
        }
    }
    __syncthreads();
    for (int r = t; r < NUM_ROIS; r += blockDim.x) {
        int sz = s_size[r];
        int rank = 0;
        for (int j = 0; j < NUM_ROIS; j++) {
            int sj = s_size[j];
            if (sj > sz || (sj == sz && j < r)) rank++;
        }
        g_order[rank] = r;
    }
}

// ============================================================
// Stage A (TC path): per-ROI tcgen05 bf16-split GEMM + BN + leaky
// one CTA per ROI; M=512 as 4 quarters of 128; N=64 (max_out<=62)
// ============================================================
#define ATC_COEF   16
#define ATC_STAGE  1024
#define ATC_XH     35840          // 1024 + 128*68*4
#define ATC_XL     52224
#define ATC_WH     68608
#define ATC_WL     76800
#define ATC_SMEM   84992

__global__ __launch_bounds__(256, 2)
void roi_enc_tc(const float* __restrict__ x, const float* __restrict__ W_enc,
                const float* __restrict__ b_enc, const float* __restrict__ gamma,
                const float* __restrict__ beta, const float* __restrict__ rmean,
                const float* __restrict__ rvar, float* __restrict__ concat_out,
                int total, int max_in, int max_out, int C)
{
#if HAVE_TC
    extern __shared__ char smem[];
    const unsigned sb = sptr(smem);
    const int tid = threadIdx.x, wid = tid >> 5, lane = tid & 31;

    const int r    = g_order[blockIdx.x];
    const int size = g_size[r];
    const int red  = g_red[r];
    const int base = g_base[r];
    const int ooff = g_off[r];
    const float* wg = W_enc + (size_t)r * max_out * max_in;

    if (wid == 0)
        asm volatile("tcgen05.alloc.cta_group::1.sync.aligned.shared::cta.b32 [%0], %1;"
                     :: "r"(sb), "r"(256u) : "memory");
    __syncthreads();
    uint32_t tmem;
    asm volatile("ld.shared.b32 %0, [%1];" : "=r"(tmem) : "r"(sb));
    if (tid == 0) mbar_init(sb + 8, 1);

    // BN coefficients: y = z*a + c
    if (tid < 64) {
        float a = 0.f, c = 0.f;
        if (tid < red) {
            size_t po = (size_t)r * max_out + tid;
            float inv = rsqrtf(rvar[po] + EPSV);
            a = gamma[po] * inv;
            c = (b_enc[po] - rmean[po]) * a + beta[po];
        }
        *(float2*)(smem + ATC_COEF + tid * 8) = make_float2(a, c);
    }
    __syncthreads();

    float* stage = (float*)(smem + ATC_STAGE);
    const unsigned stage_u = sb + ATC_STAGE;

    const int ntiles = (size + 63) >> 6;
    const int G = ntiles * 4;

    auto fill = [&](int gg) {
        int kt = gg >> 2, q = gg & 3;
        int c  = tid & 63;
        int rb = tid >> 6;
        int k  = kt * 64 + c;
        if (k < size) {
            const float* src = x + (size_t)(q * 128) * total + base + k;
            #pragma unroll
            for (int s = 0; s < 32; s++) {
                int row = rb + 4 * s;
                cpa4(stage_u + (unsigned)(68 * row + c) * 4u, src + (size_t)row * total);
            }
        } else {
            #pragma unroll
            for (int s = 0; s < 32; s++) stage[68 * (rb + 4 * s) + c] = 0.f;
        }
    };

    const uint32_t idescA = (8u << 24) | (8u << 17) | (1u << 10) | (1u << 7) | (1u << 4);
    const uint64_t DB = (2ull << 61) | (1ull << 46) | (64ull << 32) | (1ull << 16);
    const uint64_t dxh = DB | ((uint64_t)((sb + ATC_XH) >> 4) & 0x3FFF);
    const uint64_t dxl = DB | ((uint64_t)((sb + ATC_XL) >> 4) & 0x3FFF);
    const uint64_t dwh = DB | ((uint64_t)((sb + ATC_WH) >> 4) & 0x3FFF);
    const uint64_t dwl = DB | ((uint64_t)((sb + ATC_WL) >> 4) & 0x3FFF);

    const int crow = tid >> 1, chalf = tid & 1;     // convert: row, col-half
    const int wpi  = tid & 31, wob = tid >> 5;      // W load: pair, row-base

    float wv[16];
    fill(0); cp_commit();

    for (int g = 0; g < G; g++) {
        const int kt = g >> 2, q = g & 3;

        if (q == 0) {       // W tile registers (guarded scalar loads)
            #pragma unroll
            for (int i = 0; i < 8; i++) {
                int o  = wob + 8 * i;
                int k0 = kt * 64 + 2 * wpi;
                bool vo = (o < max_out);
                wv[2 * i]     = (vo && k0     < size) ? wg[(size_t)o * max_in + k0]     : 0.f;
                wv[2 * i + 1] = (vo && k0 + 1 < size) ? wg[(size_t)o * max_in + k0 + 1] : 0.f;
            }
        }

        cp_wait0();
        __syncthreads();   // FIX: cp.async completion is per-thread; barrier
                           // required before reading other threads' copies
        // convert x tile (32 f32/thread) to hi/lo pair registers
        float vx[32];
        #pragma unroll
        for (int j = 0; j < 8; j++) {
            float4 v = *(const float4*)(stage + 68 * crow + 32 * chalf + 4 * j);
            vx[4 * j] = v.x; vx[4 * j + 1] = v.y; vx[4 * j + 2] = v.z; vx[4 * j + 3] = v.w;
        }
        uint32_t xh[16], xl[16];
        #pragma unroll
        for (int p = 0; p < 16; p++) {
            float r0, r1;
            xh[p] = bf16pack(vx[2 * p], vx[2 * p + 1], r0, r1);
            xl[p] = bf16pack2(r0, r1);
        }
        __syncthreads();                       // all stage reads done
        if (g + 1 < G) fill(g + 1);
        cp_commit();
        if (g > 0) mbar_wait(sb + 8, (uint32_t)((g - 1) & 1));   // operands free

        // STS x operands (SW128)
        #pragma unroll
        for (int j2 = 0; j2 < 4; j2++) {
            unsigned off = (unsigned)(crow * 128 + 64 * chalf + 16 * j2);
            unsigned sw  = off ^ ((off >> 3) & 0x70);
            *(uint4*)(smem + ATC_XH + sw) =
                make_uint4(xh[4 * j2], xh[4 * j2 + 1], xh[4 * j2 + 2], xh[4 * j2 + 3]);
            *(uint4*)(smem + ATC_XL + sw) =
                make_uint4(xl[4 * j2], xl[4 * j2 + 1], xl[4 * j2 + 2], xl[4 * j2 + 3]);
        }
        if (q == 0) {       // STS W operands
            #pragma unroll
            for (int i = 0; i < 8; i++) {
                int o = wob + 8 * i;
                float r0, r1;
                uint32_t hw = bf16pack(wv[2 * i], wv[2 * i + 1], r0, r1);
                uint32_t lw = bf16pack2(r0, r1);
                unsigned off = (unsigned)(o * 128 + 4 * wpi);
                unsigned sw  = off ^ ((off >> 3) & 0x70);
                *(uint32_t*)(smem + ATC_WH + sw) = hw;
                *(uint32_t*)(smem + ATC_WL + sw) = lw;
            }
        }
        asm volatile("fence.proxy.async.shared::cta;" ::: "memory");
        __syncthreads();

        if (wid == 0 && elect1()) {
            uint32_t D = tmem + (uint32_t)(q * 64);
            #pragma unroll
            for (int st = 0; st < 4; st++) {
                uint32_t en0 = (kt > 0 || st > 0) ? 1u : 0u;
                mma_bf16_ss(D, dxh + st * 2, dwh + st * 2, idescA, en0);
                mma_bf16_ss(D, dxh + st * 2, dwl + st * 2, idescA, 1u);
                mma_bf16_ss(D, dxl + st * 2, dwh + st * 2, idescA, 1u);
            }
            tc_commit(sb + 8);
        }
    }
    mbar_wait(sb + 8, (uint32_t)((G - 1) & 1));
    asm volatile("tcgen05.fence::after_thread_sync;" ::: "memory");
    __syncthreads();

    // epilogue: TMEM -> BN/leaky -> smem transpose -> coalesced stores
    float* trans = stage;     // 128 x 66 floats, reuse staging region
    const int rloc  = (wid & 3) * 32 + lane;
    const int obase = (wid >> 2) * 32;
    for (int q = 0; q < 4; q++) {
        uint32_t rr[32];
        tc_ldx32(rr, tmem + (uint32_t)(q * 64 + obase));
        asm volatile("tcgen05.wait::ld.sync.aligned;" ::: "memory");
        #pragma unroll
        for (int j = 0; j < 32; j++) {
            int o = obase + j;
            float2 ac = *(const float2*)(smem + ATC_COEF + o * 8);
            float yv = __uint_as_float(rr[j]) * ac.x + ac.y;
            yv = (yv > 0.f) ? yv : SLOPEV * yv;
            trans[rloc * 66 + o] = yv;
        }
        __syncthreads();
        int oc = tid & 63;
        if (oc < red) {
            #pragma unroll
            for (int i2 = 0; i2 < 32; i2++) {
                int rw = (tid >> 6) + 4 * i2;
                concat_out[(size_t)(q * 128 + rw) * C + ooff + oc] = trans[rw * 66 + oc];
            }
        }
        __syncthreads();
    }
    if (wid == 0)
        asm volatile("tcgen05.dealloc.cta_group::1.sync.aligned.b32 %0, %1;"
                     :: "r"(tmem), "r"(256u));
#endif
}

// ============================================================
// Stage A (fallback path): R7 FFMA2 version (active when !HAVE_TC)
// ============================================================
#define A_XSTR 260
#define A_WSTR 100
#define A_XSZ  (16 * A_XSTR)
#define A_WSZ  (16 * A_WSTR)
#define A_SMEM ((2 * A_XSZ + 2 * A_WSZ) * 4)

__global__ __launch_bounds__(256, 2)
void roi_enc_kernel(const float* __restrict__ x, const float* __restrict__ W_enc,
                    const float* __restrict__ b_enc, const float* __restrict__ gamma,
                    const float* __restrict__ beta, const float* __restrict__ rmean,
                    const float* __restrict__ rvar, float* __restrict__ concat_out,
                    int total, int max_in, int max_out, int C)
{
#if HAVE_TC
    return;
#else
    extern __shared__ float sm[];
    float* Xs = sm;
    float* Ws = sm + 2 * A_XSZ;

    const int r    = g_order[blockIdx.x];
    const int b0   = blockIdx.y * 256;
    const int ot   = blockIdx.z * 32;
    const int size = g_size[r];
    const int red  = g_red[r];
    const int base = g_base[r];
    const int ooff = g_off[r];
    if (ot >= red) return;

    const int tid = threadIdx.x;
    const int tb  = tid >> 3;
    const int to  = tid & 7;
    const int fk  = tid & 15;
    const int fr0 = tid >> 4;

    const float* xg = x + (size_t)b0 * total + base;
    const float* wg = W_enc + (size_t)r * max_out * max_in;
    const unsigned xs_u = sptr(Xs);

    const int nt = (size + 15) >> 4;

    u64 acc[4][4];
    #pragma unroll
    for (int i = 0; i < 4; i++)
        #pragma unroll
        for (int j = 0; j < 4; j++) acc[i][j] = 0ull;

    float wr[2];

    auto fillX = [&](int t, int st) {
        int kg = t * 16 + fk;
        if (kg < size) {
            const float* src = xg + kg;
            unsigned dst = xs_u + (unsigned)(st * A_XSZ + fk * A_XSTR) * 4u;
            #pragma unroll
            for (int it = 0; it < 16; it++) {
                int b = fr0 + it * 16;
                cpa4(dst + (unsigned)b * 4u, src + (size_t)b * total);
            }
        } else {
            float* d = Xs + st * A_XSZ + fk * A_XSTR;
            #pragma unroll
            for (int it = 0; it < 16; it++) d[fr0 + it * 16] = 0.f;
        }
    };
    auto ldgW = [&](int t) {
        int kg = t * 16 + fk;
        #pragma unroll
        for (int it = 0; it < 2; it++) {
            int o = ot + fr0 + it * 16;
            wr[it] = (o < max_out && kg < size) ? wg[(size_t)o * max_in + kg] : 0.f;
        }
    };
    auto stsW = [&](int st) {
        float* d = Ws + st * A_WSZ + fk * A_WSTR;
        #pragma unroll
        for (int it = 0; it < 2; it++) {
            int o = fr0 + it * 16;
            *(float2*)(d + (o >> 2) * 12 + (o & 3) * 2) = make_float2(wr[it], wr[it]);
        }
    };
    auto compute = [&](int st) {
        const float* xb = Xs + st * A_XSZ + tb * 8;
        const float* wb = Ws + st * A_WSZ + to * 12;
        #pragma unroll
        for (int kk = 0; kk < 16; kk++) {
            const ulonglong2* xp = (const ulonglong2*)(xb + kk * A_XSTR);
            const ulonglong2* wp = (const ulonglong2*)(wb + kk * A_WSTR);
            ulonglong2 x01 = xp[0], x23 = xp[1];
            ulonglong2 w01 = wp[0], w23 = wp[1];
            u64 xv[4] = {x01.x, x01.y, x23.x, x23.y};
            u64 wv2[4] = {w01.x, w01.y, w23.x, w23.y};
            #pragma unroll
            for (int i = 0; i < 4; i++)
                #pragma unroll
                for (int j = 0; j < 4; j++)
                    acc[i][j] = fma2(xv[i], wv2[j], acc[i][j]);
        }
    };

    fillX(0, 0); cp_commit();
    ldgW(0);
    if (nt > 1) fillX(1, 1);
    cp_commit();
    stsW(0);
    if (nt > 1) ldgW(1);
    cp_wait1();
    __syncthreads();

    for (int t = 0; t < nt; t++) {
        int st = t & 1;
        compute(st);
        __syncthreads();
        if (t + 2 < nt) fillX(t + 2, st);
        cp_commit();
        if (t + 1 < nt) stsW(st ^ 1);
        if (t + 2 < nt) ldgW(t + 2);
        cp_wait1();
        __syncthreads();
    }

    float* Ysm = sm;
    for (int half = 0; half < 2; half++) {
        __syncthreads();
        if ((tb >> 4) == half) {
            int bl = (tb & 15) * 8;
            #pragma unroll
            for (int jj = 0; jj < 4; jj++) {
                int og = ot + to * 4 + jj;
                if (og < red) {
                    size_t po = (size_t)r * max_out + og;
                    float be  = b_enc[po];
                    float ga  = gamma[po];
                    float bt  = beta[po];
                    float mn  = rmean[po];
                    float inv = rsqrtf(rvar[po] + EPSV);
                    int ol = to * 4 + jj;
                    #pragma unroll
                    for (int i = 0; i < 4; i++) {
                        float2 v = unpack2(acc[i][jj]);
                        float y0 = ga * (v.x + be - mn) * inv + bt;
                        float y1 = ga * (v.y + be - mn) * inv + bt;
                        y0 = (y0 > 0.f) ? y0 : SLOPEV * y0;
                        y1 = (y1 > 0.f) ? y1 : SLOPEV * y1;
                        Ysm[(bl + 2 * i)     * 33 + ol] = y0;
                        Ysm[(bl + 2 * i + 1) * 33 + ol] = y1;
                    }
                }
            }
        }
        __syncthreads();
        for (int p = tid; p < 128 * 32; p += 256) {
            int bl = p >> 5, o = p & 31;
            int og = ot + o;
            if (og < red)
                concat_out[(size_t)(b0 + half * 128 + bl) * C + ooff + og] =
                    Ysm[bl * 33 + o];
        }
    }
#endif
}

// ============================================================
// bf16 hi/lo split conversion for stage B operands (TC path only)
// ============================================================
__global__ void conv_pair_kernel(const float* __restrict__ src, int which,
                                 int rows_valid, int C, int C64, int rows_total)
{
#if HAVE_TC
    size_t i = (size_t)blockIdx.x * blockDim.x + threadIdx.x;
    size_t npairs = (size_t)rows_total * C64 / 2;
    if (i >= npairs) return;
    int halfC = C64 >> 1;
    int m = (int)(i / halfC);
    int k = (int)(i - (size_t)m * halfC) * 2;
    float v0 = 0.f, v1 = 0.f;
    if (m < rows_valid) {
        if (k     < C) v0 = src[(size_t)m * C + k];
        if (k + 1 < C) v1 = src[(size_t)m * C + k + 1];
    }
    __nv_bfloat16 h0 = __float2bfloat16(v0);
    __nv_bfloat16 h1 = __float2bfloat16(v1);
    __nv_bfloat162 hp; hp.x = h0; hp.y = h1;
    __nv_bfloat162 lp;
    lp.x = __float2bfloat16(v0 - __bfloat162float(h0));
    lp.y = __float2bfloat16(v1 - __bfloat162float(h1));
    if (which == 0) {
        ((__nv_bfloat162*)g_Ah)[i] = hp;
        ((__nv_bfloat162*)g_Al)[i] = lp;
    } else {
        ((__nv_bfloat162*)g_Wh)[i] = hp;
        ((__nv_bfloat162*)g_Wl)[i] = lp;
    }
#endif
}

// ============================================================
// Stage B (TC path): tcgen05 bf16-split GEMM -> g_partial (split-K)
// ============================================================
#define TC_TILE 16384
#define TC_SMEM (1024 + 8 * TC_TILE)

__global__ __launch_bounds__(128, 1)
void reg_gemm_tc(int C64)
{
#if HAVE_TC
    extern __shared__ char smem[];
    const unsigned sbase = sptr(smem);
    const int tid = threadIdx.x, wid = tid >> 5, lane = tid & 31;
    const int m0 = blockIdx.x * 128, n0 = blockIdx.y * 128, s = blockIdx.z;

    const int ktiles = C64 >> 6;
    const int chunk  = (ktiles + SPLITK - 1) / SPLITK;
    const int t0 = s * chunk;
    const int nt = max(0, min(ktiles, t0 + chunk) - t0);

    if (wid == 0)
        asm volatile("tcgen05.alloc.cta_group::1.sync.aligned.shared::cta.b32 [%0], %1;"
                     :: "r"(sbase), "r"(128u) : "memory");
    __syncthreads();
    uint32_t tmem;
    asm volatile("ld.shared.b32 %0, [%1];" : "=r"(tmem) : "r"(sbase));
    if (tid == 0) mbar_init(sbase + 8, 1);
    __syncthreads();

    auto fill = [&](int kt, int st) {
        const size_t kb = (size_t)kt << 6;
        const unsigned ba = sbase + 1024 + (unsigned)(st * 4) * TC_TILE;
        const int c = tid & 7;
        #pragma unroll
        for (int p = 0; p < 8; p++) {
            int row = p * 16 + (tid >> 3);
            unsigned off = (unsigned)(row * 128 + c * 16);
            unsigned sw = off ^ ((off >> 3) & 0x70);
            size_t aoff = (size_t)(m0 + row) * C64 + kb + c * 8;
            size_t woff = (size_t)(n0 + row) * C64 + kb + c * 8;
            cp16(ba + sw,               g_Ah + aoff);
            cp16(ba + TC_TILE     + sw, g_Al + aoff);
            cp16(ba + 2 * TC_TILE + sw, g_Wh + woff);
            cp16(ba + 3 * TC_TILE + sw, g_Wl + woff);
        }
    };

    const uint32_t idesc = (8u << 24) | (16u << 17) | (1u << 10) | (1u << 7) | (1u << 4);
    const uint64_t DBASE = (2ull << 61) | (1ull << 46) | (64ull << 32) | (1ull << 16);

    if (nt > 0) {
        fill(t0, 0); cp_commit();
        if (nt > 1) fill(t0 + 1, 1);
        cp_commit();
        for (int t = 0; t < nt; t++) {
            const int st = t & 1;
            cp_wait1();
            asm volatile("fence.proxy.async.shared::cta;" ::: "memory");
            __syncthreads();
            if (wid == 0 && elect1()) {
                const unsigned ba = sbase + 1024 + (unsigned)(st * 4) * TC_TILE;
                uint64_t ah = DBASE | ((uint64_t)(ba >> 4) & 0x3FFF);
                uint64_t al = DBASE | ((uint64_t)((ba + TC_TILE) >> 4) & 0x3FFF);
                uint64_t bh = DBASE | ((uint64_t)((ba + 2 * TC_TILE) >> 4) & 0x3FFF);
                uint64_t bl = DBASE | ((uint64_t)((ba + 3 * TC_TILE) >> 4) & 0x3FFF);
                #pragma unroll
                for (int kk = 0; kk < 4; kk++) {
                    uint32_t en0 = (t > 0 || kk > 0) ? 1u : 0u;
                    mma_bf16_ss(tmem, ah + kk * 2, bh + kk * 2, idesc, en0);
                    mma_bf16_ss(tmem, ah + kk * 2, bl + kk * 2, idesc, 1u);
                    mma_bf16_ss(tmem, al + kk * 2, bh + kk * 2, idesc, 1u);
                }
                tc_commit(sbase + 8);
            }
            mbar_wait(sbase + 8, (uint32_t)(t & 1));
            if (t + 2 < nt) fill(t0 + t + 2, st);
            cp_commit();
        }
        asm volatile("tcgen05.fence::after_thread_sync;" ::: "memory");
    }
    __syncthreads();

    {
        const int m = m0 + wid * 32 + lane;
        float* drow = g_partial + ((size_t)s * BATCH + m) * N_REG;
        for (int c0 = 0; c0 < 128; c0 += 32) {
            uint32_t rr[32];
            if (nt > 0) {
                tc_ldx32(rr, tmem + c0);
                asm volatile("tcgen05.wait::ld.sync.aligned;" ::: "memory");
            } else {
                #pragma unroll
                for (int q = 0; q < 32; q++) rr[q] = 0u;
            }
            #pragma unroll
            for (int q = 0; q < 8; q++) {
                int n = n0 + c0 + q * 4;
                if (n + 3 < N_REG) {
                    *(float4*)(drow + n) = make_float4(
                        __uint_as_float(rr[q * 4]),     __uint_as_float(rr[q * 4 + 1]),
                        __uint_as_float(rr[q * 4 + 2]), __uint_as_float(rr[q * 4 + 3]));
                } else {
                    #pragma unroll
                    for (int j = 0; j < 4; j++)
                        if (n + j < N_REG) drow[n + j] = __uint_as_float(rr[q * 4 + j]);
                }
            }
        }
    }
    __syncthreads();
    if (wid == 0)
        asm volatile("tcgen05.dealloc.cta_group::1.sync.aligned.b32 %0, %1;"
                     :: "r"(tmem), "r"(128u));
#endif
}

// ============================================================
// Stage B (fallback path): R7 FFMA2 GEMM -> g_partial (split-K)
// ============================================================
#define B_ASTR 132
#define B_WSTR 324
#define B_ASZ  (16 * B_ASTR)
#define B_WSZ  (16 * B_WSTR)
#define B_SMEM ((2 * B_ASZ + 2 * B_WSZ) * 4)

__global__ __launch_bounds__(256, 2)
void reg_gemm_kernel(const float* __restrict__ A, const float* __restrict__ Wr, int C)
{
#if HAVE_TC
    return;
#else
    extern __shared__ float sm[];
    float* As = sm;
    float* Bs = sm + 2 * B_ASZ;

    const int m0 = blockIdx.x * 128;
    const int n0 = blockIdx.y * 128;
    const int s  = blockIdx.z;
    const int chunk = (C + SPLITK - 1) / SPLITK;
    const int kbeg  = s * chunk;
    const int kend  = min(C, kbeg + chunk);
    const int klen  = kend - kbeg;

    const int tid = threadIdx.x;
    const int tb  = tid >> 4;
    const int to  = tid & 15;
    const int fk  = tid & 15;
    const int fr0 = tid >> 4;

    const unsigned as_u = sptr(As);

    u64 acc[4][8];
    #pragma unroll
    for (int i = 0; i < 4; i++)
        #pragma unroll
        for (int j = 0; j < 8; j++) acc[i][j] = 0ull;

    if (klen > 0) {
        const int nt = (klen + 15) >> 4;
        float wr[8];

        auto fillA = [&](int t, int st) {
            int kg = kbeg + t * 16 + fk;
            if (kg < kend) {
                unsigned dst = as_u + (unsigned)(st * B_ASZ + fk * B_ASTR) * 4u;
                const float* src = A + kg;
                #pragma unroll
                for (int it = 0; it < 8; it++) {
                    int m = fr0 + it * 16;
                    cpa4(dst + (unsigned)m * 4u, src + (size_t)(m0 + m) * C);
                }
            } else {
                float* d = As + st * B_ASZ + fk * B_ASTR;
                #pragma unroll
                for (int it = 0; it < 8; it++) d[fr0 + it * 16] = 0.f;
            }
        };
        auto ldgW = [&](int t) {
            int kg = kbeg + t * 16 + fk;
            #pragma unroll
            for (int it = 0; it < 8; it++) {
                int n = n0 + fr0 + it * 16;
                wr[it] = (n < N_REG && kg < kend) ? Wr[(size_t)n * C + kg] : 0.f;
            }
        };
        auto stsW = [&](int st) {
            float* d = Bs + st * B_WSZ + fk * B_WSTR;
            #pragma unroll
            for (int it = 0; it < 8; it++) {
                int l = fr0 + it * 16;
                *(float2*)(d + (l >> 3) * 20 + (l & 7) * 2) = make_float2(wr[it], wr[it]);
            }
        };
        auto compute = [&](int st) {
            const float* xb = As + st * B_ASZ + tb * 8;
            const float* wb = Bs + st * B_WSZ + to * 20;
            #pragma unroll
            for (int kk = 0; kk < 16; kk++) {
                const ulonglong2* xp = (const ulonglong2*)(xb + kk * B_ASTR);
                const ulonglong2* wp = (const ulonglong2*)(wb + kk * B_WSTR);
                ulonglong2 x01 = xp[0], x23 = xp[1];
                ulonglong2 w01 = wp[0], w23 = wp[1], w45 = wp[2], w67 = wp[3];
                u64 xv[4] = {x01.x, x01.y, x23.x, x23.y};
                u64 wv[8] = {w01.x, w01.y, w23.x, w23.y, w45.x, w45.y, w67.x, w67.y};
                #pragma unroll
                for (int i = 0; i < 4; i++)
                    #pragma unroll
                    for (int j = 0; j < 8; j++)
                        acc[i][j] = fma2(xv[i], wv[j], acc[i][j]);
            }
        };

        fillA(0, 0); cp_commit();
        ldgW(0);
        if (nt > 1) fillA(1, 1);
        cp_commit();
        stsW(0);
        if (nt > 1) ldgW(1);
        cp_wait1();
        __syncthreads();

        for (int t = 0; t < nt; t++) {
            int st = t & 1;
            compute(st);
            __syncthreads();
            if (t + 2 < nt) fillA(t + 2, st);
            cp_commit();
            if (t + 1 < nt) stsW(st ^ 1);
            if (t + 2 < nt) ldgW(t + 2);
            cp_wait1();
            __syncthreads();
        }
    }

    #pragma unroll
    for (int j = 0; j < 8; j++) {
        int n = n0 + to * 8 + j;
        if (n < N_REG) {
            #pragma unroll
            for (int i = 0; i < 4; i++) {
                float2 v = unpack2(acc[i][j]);
                int m = m0 + tb * 8 + 2 * i;
                g_partial[((size_t)s * BATCH + m)     * N_REG + n] = v.x;
                g_partial[((size_t)s * BATCH + m + 1) * N_REG + n] = v.y;
            }
        }
    }
#endif
}

// ============================================================
// Split-K reduce + bias -> reg_out
// ============================================================
__global__ void reg_reduce_kernel(const float* __restrict__ b_reg,
                                  float* __restrict__ reg_out) {
    int i = blockIdx.x * blockDim.x + threadIdx.x;
    if (i >= BATCH * N_REG) return;
    int n = i % N_REG;
    float sum = b_reg[n];
    #pragma unroll
    for (int k = 0; k < SPLITK; k++)
        sum += g_partial[(size_t)k * BATCH * N_REG + i];
    reg_out[i] = sum;
}

// ============================================================
// Stage C: cls GEMV + softmax.  128 CTAs x 4 rows.
// ============================================================
#define C_ROWS 4

__global__ __launch_bounds__(256)
void cls_softmax_kernel(const float* __restrict__ reg_out,
                        const float* __restrict__ W_cls,
                        const float* __restrict__ b_cls,
                        float* __restrict__ y_pred) {
    __shared__ float rows[C_ROWS][304];
    __shared__ float lg[C_ROWS][192];

    const int m0  = blockIdx.x * C_ROWS;
    const int tid = threadIdx.x;

    for (int p = tid; p < C_ROWS * N_REG; p += 256) {
        int mi = p / N_REG, n = p % N_REG;
        rows[mi][n] = reg_out[(size_t)(m0 + mi) * N_REG + n];
    }
    __syncthreads();

    for (int q = tid; q < C_ROWS * N_CLS; q += 256) {
        int mi = q / N_CLS, n = q % N_CLS;
        const float4* w  = (const float4*)(W_cls + (size_t)n * N_REG);
        const float4* rr = (const float4*)rows[mi];
        float s0 = b_cls[n], s1 = 0.f;
        #pragma unroll 5
        for (int k4 = 0; k4 < N_REG / 4; k4++) {
            float4 a = rr[k4];
            float4 b = __ldg(&w[k4]);
            s0 = fmaf(a.x, b.x, s0);
            s1 = fmaf(a.y, b.y, s1);
            s0 = fmaf(a.z, b.z, s0);
            s1 = fmaf(a.w, b.w, s1);
        }
        lg[mi][n] = s0 + s1;
    }
    __syncthreads();

    int w = tid >> 5, lane = tid & 31;
    if (w < C_ROWS) {
        int mi = w;
        float mx = -1e30f;
        for (int n = lane; n < N_CLS; n += 32) mx = fmaxf(mx, lg[mi][n]);
        #pragma unroll
        for (int off = 16; off > 0; off >>= 1)
            mx = fmaxf(mx, __shfl_xor_sync(0xffffffff, mx, off));
        float sum = 0.f;
        for (int n = lane; n < N_CLS; n += 32) {
            float e = expf(lg[mi][n] - mx);
            lg[mi][n] = e;
            sum += e;
        }
        #pragma unroll
        for (int off = 16; off > 0; off >>= 1)
            sum += __shfl_xor_sync(0xffffffff, sum, off);
        float inv = 1.f / sum;
        for (int n = lane; n < N_CLS; n += 32)
            y_pred[(size_t)(m0 + mi) * N_CLS + n] = lg[mi][n] * inv;
    }
}

// ============================================================
// Launch
// ============================================================
extern "C" void kernel_launch(void* const* d_in, const int* in_sizes, int n_in,
                              void* d_out, int out_size) {
    const float* x     = (const float*)d_in[0];
    const float* W_enc = (const float*)d_in[1];
    const float* b_enc = (const float*)d_in[2];
    const float* gamma = (const float*)d_in[3];
    const float* beta  = (const float*)d_in[4];
    const float* rmean = (const float*)d_in[5];
    const float* rvar  = (const float*)d_in[6];
    const float* W_reg = (const float*)d_in[7];
    const float* b_reg = (const float*)d_in[8];
    const float* W_cls = (const float*)d_in[9];
    const float* b_cls = (const float*)d_in[10];
    const int*   idx   = (const int*)d_in[11];
    const int*   srci  = (const int*)d_in[12];

    const int total   = in_sizes[0] / BATCH;
    const int max_out = in_sizes[2] / NUM_ROIS;
    const int max_in  = in_sizes[11] / NUM_ROIS;
    const int C       = in_sizes[12];
    const int C64     = ((C + 63) / 64) * 64;

    float* out        = (float*)d_out;
    float* concat_out = out;
    float* reg_out    = out + (size_t)BATCH * C;
    float* y_pred     = reg_out + (size_t)BATCH * N_REG;

    cudaFuncSetAttribute(roi_enc_tc,
                         cudaFuncAttributeMaxDynamicSharedMemorySize, ATC_SMEM);
    cudaFuncSetAttribute(roi_enc_kernel,
                         cudaFuncAttributeMaxDynamicSharedMemorySize, A_SMEM);
    cudaFuncSetAttribute(reg_gemm_tc,
                         cudaFuncAttributeMaxDynamicSharedMemorySize, TC_SMEM);
    cudaFuncSetAttribute(reg_gemm_kernel,
                         cudaFuncAttributeMaxDynamicSharedMemorySize, B_SMEM);

    setup_kernel<<<1, 512>>>(idx, srci, max_in, max_out, total, C);

    // stage-B W conversion (no-op in fallback cubin), independent of stage A
    {
        size_t npairs = (size_t)WROWS * C64 / 2;
        conv_pair_kernel<<<(int)((npairs + 255) / 256), 256>>>(W_reg, 1, N_REG, C, C64, WROWS);
    }

    // stage A: TC kernel (no-op in fallback cubin) + fallback (no-op in TC cubin)
    roi_enc_tc<<<NUM_ROIS, 256, ATC_SMEM>>>(x, W_enc, b_enc, gamma, beta, rmean, rvar,
                                            concat_out, total, max_in, max_out, C);
    dim3 gA(NUM_ROIS, BATCH / 256, 2);
    roi_enc_kernel<<<gA, 256, A_SMEM>>>(x, W_enc, b_enc, gamma, beta, rmean, rvar,
                                        concat_out, total, max_in, max_out, C);

    // stage-B A-matrix conversion (no-op in fallback cubin)
    {
        size_t npairs = (size_t)BATCH * C64 / 2;
        conv_pair_kernel<<<(int)((npairs + 255) / 256), 256>>>(concat_out, 0, BATCH, C, C64, BATCH);
    }

    dim3 gTC(BATCH / 128, 3, SPLITK);
    reg_gemm_tc<<<gTC, 128, TC_SMEM>>>(C64);

    dim3 gB(BATCH / 128, (N_REG + 127) / 128, SPLITK);
    reg_gemm_kernel<<<gB, 256, B_SMEM>>>(concat_out, W_reg, C);

    reg_reduce_kernel<<<(BATCH * N_REG + 255) / 256, 256>>>(b_reg, reg_out);

    cls_softmax_kernel<<<BATCH / C_ROWS, 256>>>(reg_out, W_cls, b_cls, y_pred);
}